// round 13
// baseline (speedup 1.0000x reference)
#include <cuda_runtime.h>
#include <cuda_bf16.h>
#include <cuda_fp16.h>
#include <math.h>
#include <stdint.h>

// Problem constants
#define B_  2
#define S_  2048
#define H_  4096
#define NH_ 32
#define NKV_ 8
#define HD_ 128
#define M_  (B_ * S_)          // 4096 rows
#define QN_ (NH_ * HD_)        // 4096
#define KN_ (NKV_ * HD_)       // 1024
#define QKV_N (QN_ + 2 * KN_)  // 6144

// Scratch (device globals; no allocations allowed)
__device__ __half g_Xh[M_ * H_];          // fp16-rounded X
__device__ __half g_Wqkvh[H_ * QKV_N];    // concat fp16 weights [H][6144]
__device__ float  g_bqkv[QKV_N];
__device__ __half g_Woh[QN_ * H_];        // fp16 Wo
__device__ __half g_AOh[M_ * QN_];        // attention output (fp16)
__device__ __half g_Qhi[M_ * QN_], g_Qlo[M_ * QN_];   // roped+scaled Q hi/lo
__device__ __half g_Khi[M_ * KN_], g_Klo[M_ * KN_];   // roped K hi/lo
__device__ __half g_Vhi[M_ * KN_];                    // V single fp16
__device__ float2 g_rope[S_ * 64];                    // (cos, sin) per (pos, i)

__device__ __forceinline__ void st_half4(__half* p, float4 v)
{
    *(__half2*)(p)     = __floats2half2_rn(v.x, v.y);
    *(__half2*)(p + 2) = __floats2half2_rn(v.z, v.w);
}

// ---------------------------------------------------------------------------
// Fused prep: fp16 conversions + weight concat + bias concat + rope table.
// ---------------------------------------------------------------------------
#define SEG0 (M_ * H_ / 4)
#define SEG1 (H_ * QKV_N / 4)
#define SEG2 (QN_ * H_ / 4)
#define SEG3 (QKV_N / 4)
#define SEG4 (S_ * 64)
#define SEG_TOTAL (SEG0 + SEG1 + SEG2 + SEG3 + SEG4)

__global__ __launch_bounds__(256)
void prep_all(const float* __restrict__ X,
              const float* __restrict__ Wq, const float* __restrict__ Wk,
              const float* __restrict__ Wv, const float* __restrict__ Wo,
              const float* __restrict__ bq, const float* __restrict__ bk,
              const float* __restrict__ bv,
              __half* __restrict__ Xh, __half* __restrict__ Wqkvh,
              __half* __restrict__ Woh, float* __restrict__ bqkv,
              float2* __restrict__ ropeT)
{
    const int stride = gridDim.x * 256;
    for (int u = blockIdx.x * 256 + threadIdx.x; u < SEG_TOTAL; u += stride) {
        if (u < SEG0) {
            st_half4(Xh + (size_t)u * 4, *(const float4*)(X + (size_t)u * 4));
        } else if (u < SEG0 + SEG1) {
            const int j = u - SEG0;
            const int row = j / (QKV_N / 4);
            const int c = (j - row * (QKV_N / 4)) * 4;
            float4 v;
            if (c < QN_)
                v = *(const float4*)(Wq + (size_t)row * QN_ + c);
            else if (c < QN_ + KN_)
                v = *(const float4*)(Wk + (size_t)row * KN_ + (c - QN_));
            else
                v = *(const float4*)(Wv + (size_t)row * KN_ + (c - QN_ - KN_));
            st_half4(Wqkvh + (size_t)row * QKV_N + c, v);
        } else if (u < SEG0 + SEG1 + SEG2) {
            const int j = u - SEG0 - SEG1;
            st_half4(Woh + (size_t)j * 4, *(const float4*)(Wo + (size_t)j * 4));
        } else if (u < SEG0 + SEG1 + SEG2 + SEG3) {
            const int j = u - SEG0 - SEG1 - SEG2;
            const int c = j * 4;
            float4 v;
            if (c < QN_)            v = *(const float4*)(bq + c);
            else if (c < QN_ + KN_) v = *(const float4*)(bk + c - QN_);
            else                    v = *(const float4*)(bv + c - QN_ - KN_);
            *(float4*)(bqkv + c) = v;
        } else {
            const int j = u - SEG0 - SEG1 - SEG2 - SEG3;
            const int pos = j >> 6, i = j & 63;
            // identical math to the previous rope path (bit-identical results)
            const float inv_freq = exp2f(-(float)(2 * i) * (1.0f / 128.0f) * 13.28771238f);
            float c, s;
            sincosf((float)pos * inv_freq, &s, &c);
            ropeT[j] = make_float2(c, s);
        }
    }
}

// ---------------------------------------------------------------------------
// Shared MMA / ldmatrix helpers
// ---------------------------------------------------------------------------
__device__ __forceinline__ void cp_async16(void* smem_dst, const void* gsrc) {
    unsigned dst = (unsigned)__cvta_generic_to_shared(smem_dst);
    asm volatile("cp.async.cg.shared.global [%0], [%1], 16;" :: "r"(dst), "l"(gsrc));
}

__device__ __forceinline__ void ldsm4(unsigned r[4], const void* p)
{
    unsigned a = (unsigned)__cvta_generic_to_shared(p);
    asm volatile(
        "ldmatrix.sync.aligned.m8n8.x4.shared.b16 {%0,%1,%2,%3}, [%4];"
        : "=r"(r[0]), "=r"(r[1]), "=r"(r[2]), "=r"(r[3]) : "r"(a));
}

__device__ __forceinline__ void ldsm4t(unsigned r[4], const void* p)
{
    unsigned a = (unsigned)__cvta_generic_to_shared(p);
    asm volatile(
        "ldmatrix.sync.aligned.m8n8.x4.trans.shared.b16 {%0,%1,%2,%3}, [%4];"
        : "=r"(r[0]), "=r"(r[1]), "=r"(r[2]), "=r"(r[3]) : "r"(a));
}

__device__ __forceinline__ void mma_fp16(float c[4], const unsigned a[4],
                                         unsigned b0, unsigned b1)
{
    asm volatile(
        "mma.sync.aligned.m16n8k16.row.col.f32.f16.f16.f32 "
        "{%0,%1,%2,%3}, {%4,%5,%6,%7}, {%8,%9}, {%0,%1,%2,%3};"
        : "+f"(c[0]), "+f"(c[1]), "+f"(c[2]), "+f"(c[3])
        : "r"(a[0]), "r"(a[1]), "r"(a[2]), "r"(a[3]), "r"(b0), "r"(b1));
}

// ---------------------------------------------------------------------------
// GEMM tiling constants (128x128, BK=32, 3-stage)
// ---------------------------------------------------------------------------
#define FA_STR 40
#define FB_STR 136
#define FSTG (128 * FA_STR + 32 * FB_STR)
#define G_SMEM (3 * FSTG * 2)                  // 56832 B (pipeline)
#define TSTR 132
#define QKV_SMEM (128 * TSTR * 4)              // 67584 B (rope tile; >= G_SMEM)

// Mainloop body shared by both GEMMs: all LDSM hoisted before MMAs,
// MMA issue order identical to R12 (ks -> mt -> nt) => bit-identical acc.
#define GEMM_MAINLOOP(A_, B_PTR, N_, K_)                                          \
    const int KT = (K_) / 32;                                                     \
    load_stage(0, 0);                                                             \
    load_stage(1, 32);                                                            \
    for (int kt = 0; kt < KT; kt++) {                                             \
        const int s = kt % 3;                                                     \
        if (kt + 1 < KT) asm volatile("cp.async.wait_group 1;");                  \
        else             asm volatile("cp.async.wait_group 0;");                  \
        __syncthreads();                                                          \
        if (kt + 2 < KT) load_stage((kt + 2) % 3, (kt + 2) * 32);                 \
        const __half* As = gsm + s * FSTG;                                        \
        const __half* Bs = As + 128 * FA_STR;                                     \
        unsigned af[2][4][4], bf[2][4][2];                                        \
        _Pragma("unroll")                                                         \
        for (int ks = 0; ks < 2; ks++) {                                          \
            _Pragma("unroll")                                                     \
            for (int mt = 0; mt < 4; mt++)                                        \
                ldsm4(af[ks][mt], As + (warp_m + mt * 16 + ldr) * FA_STR + ks * 16 + ldc8); \
            _Pragma("unroll")                                                     \
            for (int nt2 = 0; nt2 < 2; nt2++) {                                   \
                unsigned t4[4];                                                   \
                ldsm4t(t4, Bs + (ks * 16 + ldr) * FB_STR + warp_n + nt2 * 16 + ldc8); \
                bf[ks][2 * nt2][0]     = t4[0];                                   \
                bf[ks][2 * nt2][1]     = t4[1];                                   \
                bf[ks][2 * nt2 + 1][0] = t4[2];                                   \
                bf[ks][2 * nt2 + 1][1] = t4[3];                                   \
            }                                                                     \
        }                                                                         \
        _Pragma("unroll")                                                         \
        for (int ks = 0; ks < 2; ks++)                                            \
            _Pragma("unroll")                                                     \
            for (int mt = 0; mt < 4; mt++)                                        \
                _Pragma("unroll")                                                 \
                for (int nt = 0; nt < 4; nt++)                                    \
                    mma_fp16(acc[mt][nt], af[ks][mt], bf[ks][nt][0], bf[ks][nt][1]); \
    }

// ---------------------------------------------------------------------------
// Plain FP16 GEMM (O projection)
// ---------------------------------------------------------------------------
__global__ __launch_bounds__(256)
void gemm_fp16(const __half* __restrict__ A, const __half* __restrict__ B,
               const float* __restrict__ bias, float* __restrict__ C,
               int M, int N, int K)
{
    extern __shared__ __half gsm[];

    const int tid  = threadIdx.x;
    const int wid  = tid >> 5;
    const int lane = tid & 31;
    const int warp_m = (wid & 1) * 64;
    const int warp_n = (wid >> 1) * 32;
    const int brow = blockIdx.y * 128;
    const int bcol = blockIdx.x * 128;
    const int lr = lane >> 2;
    const int lc = lane & 3;
    const int ldr  = (lane & 7) + ((lane >> 3) & 1) * 8;
    const int ldc8 = ((lane >> 4) & 1) * 8;

    float acc[4][4][4];
#pragma unroll
    for (int mt = 0; mt < 4; mt++)
#pragma unroll
        for (int nt = 0; nt < 4; nt++)
#pragma unroll
            for (int i = 0; i < 4; i++) acc[mt][nt][i] = 0.f;

    auto load_stage = [&](int s, int k0) {
        __half* As = gsm + s * FSTG;
        __half* Bs = As + 128 * FA_STR;
#pragma unroll
        for (int it = 0; it < 2; it++) {
            const int idx = tid + 256 * it;
            const int r = idx >> 2, c = (idx & 3) * 8;
            cp_async16(&As[r * FA_STR + c], &A[(size_t)(brow + r) * K + k0 + c]);
        }
#pragma unroll
        for (int it = 0; it < 2; it++) {
            const int idx = tid + 256 * it;
            const int r = idx >> 4, c = (idx & 15) * 8;
            cp_async16(&Bs[r * FB_STR + c], &B[(size_t)(k0 + r) * N + bcol + c]);
        }
        asm volatile("cp.async.commit_group;");
    };

    GEMM_MAINLOOP(A, B, N, K)

#pragma unroll
    for (int mt = 0; mt < 4; mt++) {
#pragma unroll
        for (int nt = 0; nt < 4; nt++) {
            const int row0 = brow + warp_m + mt * 16 + lr;
            const int col  = bcol + warp_n + nt * 8 + lc * 2;
            const float b0 = bias ? bias[col]     : 0.f;
            const float b1 = bias ? bias[col + 1] : 0.f;
            float2 v0 = make_float2(acc[mt][nt][0] + b0, acc[mt][nt][1] + b1);
            float2 v1 = make_float2(acc[mt][nt][2] + b0, acc[mt][nt][3] + b1);
            *(float2*)&C[(size_t)row0 * N + col]       = v0;
            *(float2*)&C[(size_t)(row0 + 8) * N + col] = v1;
        }
    }
}

// ---------------------------------------------------------------------------
// QKV GEMM with fused RoPE epilogue (table-based sincos).
// ---------------------------------------------------------------------------
__global__ __launch_bounds__(256)
void gemm_qkv_rope(const __half* __restrict__ A, const __half* __restrict__ B,
                   const float* __restrict__ bias, const int* __restrict__ pos_ids,
                   const float2* __restrict__ ropeT,
                   __half* __restrict__ Qhi, __half* __restrict__ Qlo,
                   __half* __restrict__ Khi, __half* __restrict__ Klo,
                   __half* __restrict__ Vhi)
{
    extern __shared__ __half gsm[];
    const int N = QKV_N, K = H_;

    const int tid  = threadIdx.x;
    const int wid  = tid >> 5;
    const int lane = tid & 31;
    const int warp_m = (wid & 1) * 64;
    const int warp_n = (wid >> 1) * 32;
    const int brow = blockIdx.y * 128;
    const int bcol = blockIdx.x * 128;
    const int lr = lane >> 2;
    const int lc = lane & 3;
    const int ldr  = (lane & 7) + ((lane >> 3) & 1) * 8;
    const int ldc8 = ((lane >> 4) & 1) * 8;

    float acc[4][4][4];
#pragma unroll
    for (int mt = 0; mt < 4; mt++)
#pragma unroll
        for (int nt = 0; nt < 4; nt++)
#pragma unroll
            for (int i = 0; i < 4; i++) acc[mt][nt][i] = 0.f;

    auto load_stage = [&](int s, int k0) {
        __half* As = gsm + s * FSTG;
        __half* Bs = As + 128 * FA_STR;
#pragma unroll
        for (int it = 0; it < 2; it++) {
            const int idx = tid + 256 * it;
            const int r = idx >> 2, c = (idx & 3) * 8;
            cp_async16(&As[r * FA_STR + c], &A[(size_t)(brow + r) * K + k0 + c]);
        }
#pragma unroll
        for (int it = 0; it < 2; it++) {
            const int idx = tid + 256 * it;
            const int r = idx >> 4, c = (idx & 15) * 8;
            cp_async16(&Bs[r * FB_STR + c], &B[(size_t)(k0 + r) * N + bcol + c]);
        }
        asm volatile("cp.async.commit_group;");
    };

    GEMM_MAINLOOP(A, B, N, K)

    // ---- epilogue: stage acc+bias in smem fp32, then rope + fp16 split ----
    __syncthreads();
    float* tile = reinterpret_cast<float*>(gsm);

#pragma unroll
    for (int mt = 0; mt < 4; mt++) {
#pragma unroll
        for (int nt = 0; nt < 4; nt++) {
            const int r0 = warp_m + mt * 16 + lr;
            const int c  = warp_n + nt * 8 + lc * 2;
            const float b0 = bias[bcol + c];
            const float b1 = bias[bcol + c + 1];
            tile[r0 * TSTR + c]           = acc[mt][nt][0] + b0;
            tile[r0 * TSTR + c + 1]       = acc[mt][nt][1] + b1;
            tile[(r0 + 8) * TSTR + c]     = acc[mt][nt][2] + b0;
            tile[(r0 + 8) * TSTR + c + 1] = acc[mt][nt][3] + b1;
        }
    }
    __syncthreads();

    const int head = blockIdx.x;

#pragma unroll
    for (int mt = 0; mt < 4; mt++) {
#pragma unroll
        for (int rr = 0; rr < 2; rr++) {
            const int rl = warp_m + mt * 16 + lr + rr * 8;
            const int grow = brow + rl;
            const int pos = pos_ids[grow];

#pragma unroll
            for (int nt = 0; nt < 4; nt++) {
                const int c = warp_n + nt * 8 + lc * 2;
                float v0 = tile[rl * TSTR + c];
                float v1 = tile[rl * TSTR + c + 1];

                if (head < NH_ + NKV_) {
                    const int poff = (c < 64) ? 64 : -64;
                    const float sgn = (c < 64) ? -1.f : 1.f;
                    const float o0 = sgn * tile[rl * TSTR + c + poff];
                    const float o1 = sgn * tile[rl * TSTR + c + 1 + poff];

                    const float2 cs0 = ropeT[pos * 64 + (c & 63)];
                    const float2 cs1 = ropeT[pos * 64 + ((c + 1) & 63)];
                    v0 = v0 * cs0.x + o0 * cs0.y;
                    v1 = v1 * cs1.x + o1 * cs1.y;

                    if (head < NH_) {
                        v0 *= 0.08838834764831845f;
                        v1 *= 0.08838834764831845f;
                        const size_t off = (size_t)grow * QN_ + head * HD_ + c;
                        __half2 h = __floats2half2_rn(v0, v1);
                        float hx = __low2float(h), hy = __high2float(h);
                        *(__half2*)(Qhi + off) = h;
                        *(__half2*)(Qlo + off) = __floats2half2_rn(v0 - hx, v1 - hy);
                    } else {
                        const size_t off = (size_t)grow * KN_ + (head - NH_) * HD_ + c;
                        __half2 h = __floats2half2_rn(v0, v1);
                        float hx = __low2float(h), hy = __high2float(h);
                        *(__half2*)(Khi + off) = h;
                        *(__half2*)(Klo + off) = __floats2half2_rn(v0 - hx, v1 - hy);
                    }
                } else {
                    const size_t off = (size_t)grow * KN_ + (head - NH_ - NKV_) * HD_ + c;
                    *(__half2*)(Vhi + off) = __floats2half2_rn(v0, v1);
                }
            }
        }
    }
}

// ---------------------------------------------------------------------------
// Tensor-core flash attention (unchanged from R12): QK 3-MMA, PV 1-MMA.
// ---------------------------------------------------------------------------
#define BQ 64
#define BK 64
#define KSTR 136
#define ABUF (BK * KSTR * 2)
#define ATT_SMEM (3 * ABUF)

__global__ __launch_bounds__(128)
void attn_mma(const __half* __restrict__ Qhi, const __half* __restrict__ Qlo,
              const __half* __restrict__ Khi, const __half* __restrict__ Klo,
              const __half* __restrict__ Vhi,
              __half* __restrict__ AOh)
{
    extern __shared__ char smraw[];
    __half* sKhi = (__half*)(smraw);
    __half* sKlo = (__half*)(smraw + ABUF);
    __half* sVhi = (__half*)(smraw + 2 * ABUF);

    const int qt = blockIdx.x, h = blockIdx.y, b = blockIdx.z;
    const int q0 = qt * BQ;
    const int kvh = h >> 2;
    const int tid = threadIdx.x;
    const int w = tid >> 5, lane = tid & 31;
    const int lr = lane >> 2, lc = lane & 3;

    const int qrow0 = q0 + w * 16 + lr;
    const int qrow1 = qrow0 + 8;

    unsigned qa_hi[8][4], qa_lo[8][4];
    {
        const size_t o0 = ((size_t)(b * S_) + qrow0) * QN_ + h * HD_;
        const size_t o1 = ((size_t)(b * S_) + qrow1) * QN_ + h * HD_;
#pragma unroll
        for (int kt = 0; kt < 8; kt++) {
            const int c0 = kt * 16 + 2 * lc;
            qa_hi[kt][0] = *(const unsigned*)(Qhi + o0 + c0);
            qa_hi[kt][1] = *(const unsigned*)(Qhi + o1 + c0);
            qa_hi[kt][2] = *(const unsigned*)(Qhi + o0 + c0 + 8);
            qa_hi[kt][3] = *(const unsigned*)(Qhi + o1 + c0 + 8);
            qa_lo[kt][0] = *(const unsigned*)(Qlo + o0 + c0);
            qa_lo[kt][1] = *(const unsigned*)(Qlo + o1 + c0);
            qa_lo[kt][2] = *(const unsigned*)(Qlo + o0 + c0 + 8);
            qa_lo[kt][3] = *(const unsigned*)(Qlo + o1 + c0 + 8);
        }
    }

    float m0 = -1e30f, m1 = -1e30f, l0 = 0.f, l1 = 0.f;
    float o[16][4];
#pragma unroll
    for (int i = 0; i < 16; i++)
#pragma unroll
        for (int j = 0; j < 4; j++) o[i][j] = 0.f;

    const int nTiles = qt + 1;
    const int wEnd = q0 + w * 16 + 16;
    const int ldr = (lane & 7) + ((lane >> 3) & 1) * 8;
    const int ldc = ((lane >> 4) & 1) * 8;
    const int klr = lane & 7;
    const int kmg = lane >> 3;

    const size_t kv_base = (size_t)(b * S_) * KN_ + kvh * HD_;

    auto load_k = [&](int kbase) {
        const size_t off = kv_base + (size_t)kbase * KN_;
#pragma unroll
        for (int j = 0; j < 8; j++) {
            const int idx = tid + 128 * j;
            const int row = idx >> 4, c16 = idx & 15;
            const size_t g = off + (size_t)row * KN_ + c16 * 8;
            cp_async16(sKhi + row * KSTR + c16 * 8, Khi + g);
            cp_async16(sKlo + row * KSTR + c16 * 8, Klo + g);
        }
        asm volatile("cp.async.commit_group;");
    };
    auto load_v = [&](int kbase) {
        const size_t off = kv_base + (size_t)kbase * KN_;
#pragma unroll
        for (int j = 0; j < 8; j++) {
            const int idx = tid + 128 * j;
            const int row = idx >> 4, c16 = idx & 15;
            cp_async16(sVhi + row * KSTR + c16 * 8, Vhi + off + (size_t)row * KN_ + c16 * 8);
        }
        asm volatile("cp.async.commit_group;");
    };

    load_k(0);
    asm volatile("cp.async.wait_group 0;");
    __syncthreads();

    for (int kt = 0; kt < nTiles; kt++) {
        const int kbase = kt * BK;
        const bool active = kbase < wEnd;

        load_v(kbase);

        float sA[8][4];
        unsigned pa[4][4];

        if (active) {
#pragma unroll
            for (int nt = 0; nt < 8; nt++)
#pragma unroll
                for (int j = 0; j < 4; j++) sA[nt][j] = 0.f;

#pragma unroll
            for (int dkt2 = 0; dkt2 < 4; dkt2++) {
                const int col = dkt2 * 32 + kmg * 8;
#pragma unroll
                for (int nt = 0; nt < 8; nt++) {
                    unsigned bh[4], bl[4];
                    ldsm4(bh, sKhi + (nt * 8 + klr) * KSTR + col);
                    ldsm4(bl, sKlo + (nt * 8 + klr) * KSTR + col);
                    mma_fp16(sA[nt], qa_hi[2 * dkt2],     bh[0], bh[1]);
                    mma_fp16(sA[nt], qa_hi[2 * dkt2],     bl[0], bl[1]);
                    mma_fp16(sA[nt], qa_lo[2 * dkt2],     bh[0], bh[1]);
                    mma_fp16(sA[nt], qa_hi[2 * dkt2 + 1], bh[2], bh[3]);
                    mma_fp16(sA[nt], qa_hi[2 * dkt2 + 1], bl[2], bl[3]);
                    mma_fp16(sA[nt], qa_lo[2 * dkt2 + 1], bh[2], bh[3]);
                }
            }

            if (kbase + BK > qrow0) {
#pragma unroll
                for (int nt = 0; nt < 8; nt++) {
                    const int j0 = kbase + nt * 8 + 2 * lc;
                    if (j0 > qrow0)     sA[nt][0] = -1e30f;
                    if (j0 + 1 > qrow0) sA[nt][1] = -1e30f;
                    if (j0 > qrow1)     sA[nt][2] = -1e30f;
                    if (j0 + 1 > qrow1) sA[nt][3] = -1e30f;
                }
            }

            float mt0 = -1e30f, mt1 = -1e30f;
#pragma unroll
            for (int nt = 0; nt < 8; nt++) {
                mt0 = fmaxf(mt0, fmaxf(sA[nt][0], sA[nt][1]));
                mt1 = fmaxf(mt1, fmaxf(sA[nt][2], sA[nt][3]));
            }
            mt0 = fmaxf(mt0, __shfl_xor_sync(0xffffffffu, mt0, 1));
            mt0 = fmaxf(mt0, __shfl_xor_sync(0xffffffffu, mt0, 2));
            mt1 = fmaxf(mt1, __shfl_xor_sync(0xffffffffu, mt1, 1));
            mt1 = fmaxf(mt1, __shfl_xor_sync(0xffffffffu, mt1, 2));

            const float nm0 = fmaxf(m0, mt0);
            const float nm1 = fmaxf(m1, mt1);
            const float al0 = __expf(m0 - nm0);
            const float al1 = __expf(m1 - nm1);

            float rs0 = 0.f, rs1 = 0.f;
#pragma unroll
            for (int nt = 0; nt < 8; nt++) {
                sA[nt][0] = __expf(sA[nt][0] - nm0);
                sA[nt][1] = __expf(sA[nt][1] - nm0);
                sA[nt][2] = __expf(sA[nt][2] - nm1);
                sA[nt][3] = __expf(sA[nt][3] - nm1);
                rs0 += sA[nt][0] + sA[nt][1];
                rs1 += sA[nt][2] + sA[nt][3];
            }
            rs0 += __shfl_xor_sync(0xffffffffu, rs0, 1);
            rs0 += __shfl_xor_sync(0xffffffffu, rs0, 2);
            rs1 += __shfl_xor_sync(0xffffffffu, rs1, 1);
            rs1 += __shfl_xor_sync(0xffffffffu, rs1, 2);

            l0 = l0 * al0 + rs0;
            l1 = l1 * al1 + rs1;
            m0 = nm0; m1 = nm1;

#pragma unroll
            for (int i = 0; i < 16; i++) {
                o[i][0] *= al0; o[i][1] *= al0;
                o[i][2] *= al1; o[i][3] *= al1;
            }

#pragma unroll
            for (int t = 0; t < 4; t++) {
                __half2 p0 = __floats2half2_rn(sA[2 * t][0],     sA[2 * t][1]);
                __half2 p1 = __floats2half2_rn(sA[2 * t][2],     sA[2 * t][3]);
                __half2 p2 = __floats2half2_rn(sA[2 * t + 1][0], sA[2 * t + 1][1]);
                __half2 p3 = __floats2half2_rn(sA[2 * t + 1][2], sA[2 * t + 1][3]);
                pa[t][0] = *(unsigned*)&p0;
                pa[t][1] = *(unsigned*)&p1;
                pa[t][2] = *(unsigned*)&p2;
                pa[t][3] = *(unsigned*)&p3;
            }
        }

        asm volatile("cp.async.wait_group 0;");
        __syncthreads();

        if (kt + 1 < nTiles) load_k(kbase + BK);

        if (active) {
#pragma unroll
            for (int t = 0; t < 4; t++) {
#pragma unroll
                for (int np = 0; np < 8; np++) {
                    unsigned vh[4];
                    ldsm4t(vh, sVhi + (t * 16 + ldr) * KSTR + np * 16 + ldc);
                    mma_fp16(o[2 * np],     pa[t], vh[0], vh[1]);
                    mma_fp16(o[2 * np + 1], pa[t], vh[2], vh[3]);
                }
            }
        }

        asm volatile("cp.async.wait_group 0;");
        __syncthreads();
    }

    const float il0 = 1.f / l0;
    const float il1 = 1.f / l1;
    __half* O0 = AOh + ((size_t)(b * S_) + qrow0) * QN_ + h * HD_;
    __half* O1 = AOh + ((size_t)(b * S_) + qrow1) * QN_ + h * HD_;
#pragma unroll
    for (int nt = 0; nt < 16; nt++) {
        *(__half2*)(O0 + nt * 8 + 2 * lc) =
            __floats2half2_rn(o[nt][0] * il0, o[nt][1] * il0);
        *(__half2*)(O1 + nt * 8 + 2 * lc) =
            __floats2half2_rn(o[nt][2] * il1, o[nt][3] * il1);
    }
}

// ---------------------------------------------------------------------------
// Launcher
// ---------------------------------------------------------------------------
extern "C" void kernel_launch(void* const* d_in, const int* in_sizes, int n_in,
                              void* d_out, int out_size)
{
    const float* X   = (const float*)d_in[0];
    const int*   pos = (const int*)  d_in[1];
    const float* Wq  = (const float*)d_in[2];
    const float* bq  = (const float*)d_in[3];
    const float* Wk  = (const float*)d_in[4];
    const float* bk  = (const float*)d_in[5];
    const float* Wv  = (const float*)d_in[6];
    const float* bv  = (const float*)d_in[7];
    const float* Wo  = (const float*)d_in[8];
    float* out = (float*)d_out;

    __half *Xh, *Wqkvh, *Woh, *AOh, *Qhi, *Qlo, *Khi, *Klo, *Vhi;
    float *bqkv;
    float2* ropeT;
    cudaGetSymbolAddress((void**)&Xh,    g_Xh);
    cudaGetSymbolAddress((void**)&Wqkvh, g_Wqkvh);
    cudaGetSymbolAddress((void**)&bqkv,  g_bqkv);
    cudaGetSymbolAddress((void**)&Woh,   g_Woh);
    cudaGetSymbolAddress((void**)&AOh,   g_AOh);
    cudaGetSymbolAddress((void**)&Qhi,   g_Qhi);
    cudaGetSymbolAddress((void**)&Qlo,   g_Qlo);
    cudaGetSymbolAddress((void**)&Khi,   g_Khi);
    cudaGetSymbolAddress((void**)&Klo,   g_Klo);
    cudaGetSymbolAddress((void**)&Vhi,   g_Vhi);
    cudaGetSymbolAddress((void**)&ropeT, g_rope);

    cudaFuncSetAttribute(attn_mma,      cudaFuncAttributeMaxDynamicSharedMemorySize, ATT_SMEM);
    cudaFuncSetAttribute(gemm_fp16,     cudaFuncAttributeMaxDynamicSharedMemorySize, G_SMEM);
    cudaFuncSetAttribute(gemm_qkv_rope, cudaFuncAttributeMaxDynamicSharedMemorySize, QKV_SMEM);

    // Fused prep (fp16 rounding + concat + bias + rope table)
    prep_all<<<1184, 256>>>(X, Wq, Wk, Wv, Wo, bq, bk, bv, Xh, Wqkvh, Woh, bqkv, ropeT);

    // Fused QKV projection + RoPE + fp16 splits
    gemm_qkv_rope<<<dim3(QKV_N / 128, M_ / 128), 256, QKV_SMEM>>>(
        Xh, Wqkvh, bqkv, pos, ropeT, Qhi, Qlo, Khi, Klo, Vhi);

    // Attention (QK 3-MMA, PV 1-MMA), writes fp16 AO
    attn_mma<<<dim3(S_ / BQ, NH_, B_), 128, ATT_SMEM>>>(Qhi, Qlo, Khi, Klo, Vhi, AOh);

    // Output projection (fp16 tensor cores)
    gemm_fp16<<<dim3(QN_ / 128, M_ / 128), 256, G_SMEM>>>(
        AOh, Woh, nullptr, out, M_, QN_, H_);
}

// round 14
// speedup vs baseline: 1.0394x; 1.0394x over previous
#include <cuda_runtime.h>
#include <cuda_bf16.h>
#include <cuda_fp16.h>
#include <math.h>
#include <stdint.h>

// Problem constants
#define B_  2
#define S_  2048
#define H_  4096
#define NH_ 32
#define NKV_ 8
#define HD_ 128
#define M_  (B_ * S_)          // 4096 rows
#define QN_ (NH_ * HD_)        // 4096
#define KN_ (NKV_ * HD_)       // 1024
#define QKV_N (QN_ + 2 * KN_)  // 6144

// Scratch (device globals; no allocations allowed)
__device__ __half g_Xh[M_ * H_];          // fp16-rounded X
__device__ __half g_Wqkvh[H_ * QKV_N];    // concat fp16 weights [H][6144]
__device__ float  g_bqkv[QKV_N];
__device__ __half g_Woh[QN_ * H_];        // fp16 Wo
__device__ __half g_AOh[M_ * QN_];        // attention output (fp16)
__device__ __half g_Qhi[M_ * QN_], g_Qlo[M_ * QN_];   // roped+scaled Q hi/lo
__device__ __half g_Khi[M_ * KN_], g_Klo[M_ * KN_];   // roped K hi/lo
__device__ __half g_Vhi[M_ * KN_];                    // V single fp16

__device__ __forceinline__ void st_half4(__half* p, float4 v)
{
    *(__half2*)(p)     = __floats2half2_rn(v.x, v.y);
    *(__half2*)(p + 2) = __floats2half2_rn(v.z, v.w);
}

// ---------------------------------------------------------------------------
// Fused prep (R12)
// ---------------------------------------------------------------------------
#define SEG0 (M_ * H_ / 4)
#define SEG1 (H_ * QKV_N / 4)
#define SEG2 (QN_ * H_ / 4)
#define SEG3 (QKV_N / 4)
#define SEG_TOTAL (SEG0 + SEG1 + SEG2 + SEG3)

__global__ __launch_bounds__(256)
void prep_all(const float* __restrict__ X,
              const float* __restrict__ Wq, const float* __restrict__ Wk,
              const float* __restrict__ Wv, const float* __restrict__ Wo,
              const float* __restrict__ bq, const float* __restrict__ bk,
              const float* __restrict__ bv,
              __half* __restrict__ Xh, __half* __restrict__ Wqkvh,
              __half* __restrict__ Woh, float* __restrict__ bqkv)
{
    const int stride = gridDim.x * 256;
    for (int u = blockIdx.x * 256 + threadIdx.x; u < SEG_TOTAL; u += stride) {
        if (u < SEG0) {
            st_half4(Xh + (size_t)u * 4, *(const float4*)(X + (size_t)u * 4));
        } else if (u < SEG0 + SEG1) {
            const int j = u - SEG0;
            const int row = j / (QKV_N / 4);
            const int c = (j - row * (QKV_N / 4)) * 4;
            float4 v;
            if (c < QN_)
                v = *(const float4*)(Wq + (size_t)row * QN_ + c);
            else if (c < QN_ + KN_)
                v = *(const float4*)(Wk + (size_t)row * KN_ + (c - QN_));
            else
                v = *(const float4*)(Wv + (size_t)row * KN_ + (c - QN_ - KN_));
            st_half4(Wqkvh + (size_t)row * QKV_N + c, v);
        } else if (u < SEG0 + SEG1 + SEG2) {
            const int j = u - SEG0 - SEG1;
            st_half4(Woh + (size_t)j * 4, *(const float4*)(Wo + (size_t)j * 4));
        } else {
            const int j = u - SEG0 - SEG1 - SEG2;
            const int c = j * 4;
            float4 v;
            if (c < QN_)            v = *(const float4*)(bq + c);
            else if (c < QN_ + KN_) v = *(const float4*)(bk + c - QN_);
            else                    v = *(const float4*)(bv + c - QN_ - KN_);
            *(float4*)(bqkv + c) = v;
        }
    }
}

// ---------------------------------------------------------------------------
// Shared MMA / ldmatrix helpers
// ---------------------------------------------------------------------------
__device__ __forceinline__ void cp_async16(void* smem_dst, const void* gsrc) {
    unsigned dst = (unsigned)__cvta_generic_to_shared(smem_dst);
    asm volatile("cp.async.cg.shared.global [%0], [%1], 16;" :: "r"(dst), "l"(gsrc));
}

__device__ __forceinline__ void ldsm4(unsigned r[4], const void* p)
{
    unsigned a = (unsigned)__cvta_generic_to_shared(p);
    asm volatile(
        "ldmatrix.sync.aligned.m8n8.x4.shared.b16 {%0,%1,%2,%3}, [%4];"
        : "=r"(r[0]), "=r"(r[1]), "=r"(r[2]), "=r"(r[3]) : "r"(a));
}

__device__ __forceinline__ void ldsm4t(unsigned r[4], const void* p)
{
    unsigned a = (unsigned)__cvta_generic_to_shared(p);
    asm volatile(
        "ldmatrix.sync.aligned.m8n8.x4.trans.shared.b16 {%0,%1,%2,%3}, [%4];"
        : "=r"(r[0]), "=r"(r[1]), "=r"(r[2]), "=r"(r[3]) : "r"(a));
}

__device__ __forceinline__ void mma_fp16(float c[4], const unsigned a[4],
                                         unsigned b0, unsigned b1)
{
    asm volatile(
        "mma.sync.aligned.m16n8k16.row.col.f32.f16.f16.f32 "
        "{%0,%1,%2,%3}, {%4,%5,%6,%7}, {%8,%9}, {%0,%1,%2,%3};"
        : "+f"(c[0]), "+f"(c[1]), "+f"(c[2]), "+f"(c[3])
        : "r"(a[0]), "r"(a[1]), "r"(a[2]), "r"(a[3]), "r"(b0), "r"(b1));
}

// ---------------------------------------------------------------------------
// GEMM tiling constants (128x128, BK=32, 3-stage) — R12 mainloop
// ---------------------------------------------------------------------------
#define FA_STR 40
#define FB_STR 136
#define FSTG (128 * FA_STR + 32 * FB_STR)
#define G_SMEM (3 * FSTG * 2)                  // 56832 B (pipeline)
#define TSTR 132
#define QKV_SMEM (128 * TSTR * 4)              // 67584 B (rope tile; >= G_SMEM)

// ---------------------------------------------------------------------------
// Plain FP16 GEMM (O projection): R12 version.
// ---------------------------------------------------------------------------
__global__ __launch_bounds__(256)
void gemm_fp16(const __half* __restrict__ A, const __half* __restrict__ B,
               const float* __restrict__ bias, float* __restrict__ C,
               int M, int N, int K)
{
    extern __shared__ __half gsm[];

    const int tid  = threadIdx.x;
    const int wid  = tid >> 5;
    const int lane = tid & 31;
    const int warp_m = (wid & 1) * 64;
    const int warp_n = (wid >> 1) * 32;
    const int brow = blockIdx.y * 128;
    const int bcol = blockIdx.x * 128;
    const int lr = lane >> 2;
    const int lc = lane & 3;
    const int ldr  = (lane & 7) + ((lane >> 3) & 1) * 8;
    const int ldc8 = ((lane >> 4) & 1) * 8;

    float acc[4][4][4];
#pragma unroll
    for (int mt = 0; mt < 4; mt++)
#pragma unroll
        for (int nt = 0; nt < 4; nt++)
#pragma unroll
            for (int i = 0; i < 4; i++) acc[mt][nt][i] = 0.f;

    auto load_stage = [&](int s, int k0) {
        __half* As = gsm + s * FSTG;
        __half* Bs = As + 128 * FA_STR;
#pragma unroll
        for (int it = 0; it < 2; it++) {
            const int idx = tid + 256 * it;
            const int r = idx >> 2, c = (idx & 3) * 8;
            cp_async16(&As[r * FA_STR + c], &A[(size_t)(brow + r) * K + k0 + c]);
        }
#pragma unroll
        for (int it = 0; it < 2; it++) {
            const int idx = tid + 256 * it;
            const int r = idx >> 4, c = (idx & 15) * 8;
            cp_async16(&Bs[r * FB_STR + c], &B[(size_t)(k0 + r) * N + bcol + c]);
        }
        asm volatile("cp.async.commit_group;");
    };

    const int KT = K / 32;
    load_stage(0, 0);
    load_stage(1, 32);

    for (int kt = 0; kt < KT; kt++) {
        const int s = kt % 3;
        if (kt + 1 < KT) asm volatile("cp.async.wait_group 1;");
        else             asm volatile("cp.async.wait_group 0;");
        __syncthreads();

        if (kt + 2 < KT) load_stage((kt + 2) % 3, (kt + 2) * 32);

        const __half* As = gsm + s * FSTG;
        const __half* Bs = As + 128 * FA_STR;

#pragma unroll
        for (int ks = 0; ks < 2; ks++) {
            unsigned af[4][4];
#pragma unroll
            for (int mt = 0; mt < 4; mt++)
                ldsm4(af[mt], As + (warp_m + mt * 16 + ldr) * FA_STR + ks * 16 + ldc8);

            unsigned bf[4][2];
#pragma unroll
            for (int nt2 = 0; nt2 < 2; nt2++) {
                unsigned t4[4];
                ldsm4t(t4, Bs + (ks * 16 + ldr) * FB_STR + warp_n + nt2 * 16 + ldc8);
                bf[2 * nt2][0]     = t4[0];
                bf[2 * nt2][1]     = t4[1];
                bf[2 * nt2 + 1][0] = t4[2];
                bf[2 * nt2 + 1][1] = t4[3];
            }

#pragma unroll
            for (int mt = 0; mt < 4; mt++)
#pragma unroll
                for (int nt = 0; nt < 4; nt++)
                    mma_fp16(acc[mt][nt], af[mt], bf[nt][0], bf[nt][1]);
        }
    }

#pragma unroll
    for (int mt = 0; mt < 4; mt++) {
#pragma unroll
        for (int nt = 0; nt < 4; nt++) {
            const int row0 = brow + warp_m + mt * 16 + lr;
            const int col  = bcol + warp_n + nt * 8 + lc * 2;
            const float b0 = bias ? bias[col]     : 0.f;
            const float b1 = bias ? bias[col + 1] : 0.f;
            float2 v0 = make_float2(acc[mt][nt][0] + b0, acc[mt][nt][1] + b1);
            float2 v1 = make_float2(acc[mt][nt][2] + b0, acc[mt][nt][3] + b1);
            *(float2*)&C[(size_t)row0 * N + col]       = v0;
            *(float2*)&C[(size_t)(row0 + 8) * N + col] = v1;
        }
    }
}

// ---------------------------------------------------------------------------
// QKV GEMM with fused RoPE epilogue (R12 version, in-epilogue sincos).
// ---------------------------------------------------------------------------
__global__ __launch_bounds__(256)
void gemm_qkv_rope(const __half* __restrict__ A, const __half* __restrict__ B,
                   const float* __restrict__ bias, const int* __restrict__ pos_ids,
                   __half* __restrict__ Qhi, __half* __restrict__ Qlo,
                   __half* __restrict__ Khi, __half* __restrict__ Klo,
                   __half* __restrict__ Vhi)
{
    extern __shared__ __half gsm[];
    const int N = QKV_N, K = H_;

    const int tid  = threadIdx.x;
    const int wid  = tid >> 5;
    const int lane = tid & 31;
    const int warp_m = (wid & 1) * 64;
    const int warp_n = (wid >> 1) * 32;
    const int brow = blockIdx.y * 128;
    const int bcol = blockIdx.x * 128;
    const int lr = lane >> 2;
    const int lc = lane & 3;
    const int ldr  = (lane & 7) + ((lane >> 3) & 1) * 8;
    const int ldc8 = ((lane >> 4) & 1) * 8;

    float acc[4][4][4];
#pragma unroll
    for (int mt = 0; mt < 4; mt++)
#pragma unroll
        for (int nt = 0; nt < 4; nt++)
#pragma unroll
            for (int i = 0; i < 4; i++) acc[mt][nt][i] = 0.f;

    auto load_stage = [&](int s, int k0) {
        __half* As = gsm + s * FSTG;
        __half* Bs = As + 128 * FA_STR;
#pragma unroll
        for (int it = 0; it < 2; it++) {
            const int idx = tid + 256 * it;
            const int r = idx >> 2, c = (idx & 3) * 8;
            cp_async16(&As[r * FA_STR + c], &A[(size_t)(brow + r) * K + k0 + c]);
        }
#pragma unroll
        for (int it = 0; it < 2; it++) {
            const int idx = tid + 256 * it;
            const int r = idx >> 4, c = (idx & 15) * 8;
            cp_async16(&Bs[r * FB_STR + c], &B[(size_t)(k0 + r) * N + bcol + c]);
        }
        asm volatile("cp.async.commit_group;");
    };

    const int KT = K / 32;
    load_stage(0, 0);
    load_stage(1, 32);

    for (int kt = 0; kt < KT; kt++) {
        const int s = kt % 3;
        if (kt + 1 < KT) asm volatile("cp.async.wait_group 1;");
        else             asm volatile("cp.async.wait_group 0;");
        __syncthreads();

        if (kt + 2 < KT) load_stage((kt + 2) % 3, (kt + 2) * 32);

        const __half* As = gsm + s * FSTG;
        const __half* Bs = As + 128 * FA_STR;

#pragma unroll
        for (int ks = 0; ks < 2; ks++) {
            unsigned af[4][4];
#pragma unroll
            for (int mt = 0; mt < 4; mt++)
                ldsm4(af[mt], As + (warp_m + mt * 16 + ldr) * FA_STR + ks * 16 + ldc8);

            unsigned bf[4][2];
#pragma unroll
            for (int nt2 = 0; nt2 < 2; nt2++) {
                unsigned t4[4];
                ldsm4t(t4, Bs + (ks * 16 + ldr) * FB_STR + warp_n + nt2 * 16 + ldc8);
                bf[2 * nt2][0]     = t4[0];
                bf[2 * nt2][1]     = t4[1];
                bf[2 * nt2 + 1][0] = t4[2];
                bf[2 * nt2 + 1][1] = t4[3];
            }

#pragma unroll
            for (int mt = 0; mt < 4; mt++)
#pragma unroll
                for (int nt = 0; nt < 4; nt++)
                    mma_fp16(acc[mt][nt], af[mt], bf[nt][0], bf[nt][1]);
        }
    }

    // ---- epilogue: stage acc+bias in smem fp32, then rope + fp16 split ----
    __syncthreads();
    float* tile = reinterpret_cast<float*>(gsm);

#pragma unroll
    for (int mt = 0; mt < 4; mt++) {
#pragma unroll
        for (int nt = 0; nt < 4; nt++) {
            const int r0 = warp_m + mt * 16 + lr;
            const int c  = warp_n + nt * 8 + lc * 2;
            const float b0 = bias[bcol + c];
            const float b1 = bias[bcol + c + 1];
            tile[r0 * TSTR + c]           = acc[mt][nt][0] + b0;
            tile[r0 * TSTR + c + 1]       = acc[mt][nt][1] + b1;
            tile[(r0 + 8) * TSTR + c]     = acc[mt][nt][2] + b0;
            tile[(r0 + 8) * TSTR + c + 1] = acc[mt][nt][3] + b1;
        }
    }
    __syncthreads();

    const int head = blockIdx.x;

#pragma unroll
    for (int mt = 0; mt < 4; mt++) {
#pragma unroll
        for (int rr = 0; rr < 2; rr++) {
            const int rl = warp_m + mt * 16 + lr + rr * 8;
            const int grow = brow + rl;
            const int pos = pos_ids[grow];

#pragma unroll
            for (int nt = 0; nt < 4; nt++) {
                const int c = warp_n + nt * 8 + lc * 2;
                float v0 = tile[rl * TSTR + c];
                float v1 = tile[rl * TSTR + c + 1];

                if (head < NH_ + NKV_) {
                    const int poff = (c < 64) ? 64 : -64;
                    const float sgn = (c < 64) ? -1.f : 1.f;
                    const float o0 = sgn * tile[rl * TSTR + c + poff];
                    const float o1 = sgn * tile[rl * TSTR + c + 1 + poff];

                    const int i0 = c & 63, i1 = (c + 1) & 63;
                    float c0, s0, c1, s1;
                    {
                        const float f0 = exp2f(-(float)(2 * i0) * (1.0f / 128.0f) * 13.28771238f);
                        sincosf((float)pos * f0, &s0, &c0);
                        const float f1 = exp2f(-(float)(2 * i1) * (1.0f / 128.0f) * 13.28771238f);
                        sincosf((float)pos * f1, &s1, &c1);
                    }
                    v0 = v0 * c0 + o0 * s0;
                    v1 = v1 * c1 + o1 * s1;

                    if (head < NH_) {
                        v0 *= 0.08838834764831845f;
                        v1 *= 0.08838834764831845f;
                        const size_t off = (size_t)grow * QN_ + head * HD_ + c;
                        __half2 h = __floats2half2_rn(v0, v1);
                        float hx = __low2float(h), hy = __high2float(h);
                        *(__half2*)(Qhi + off) = h;
                        *(__half2*)(Qlo + off) = __floats2half2_rn(v0 - hx, v1 - hy);
                    } else {
                        const size_t off = (size_t)grow * KN_ + (head - NH_) * HD_ + c;
                        __half2 h = __floats2half2_rn(v0, v1);
                        float hx = __low2float(h), hy = __high2float(h);
                        *(__half2*)(Khi + off) = h;
                        *(__half2*)(Klo + off) = __floats2half2_rn(v0 - hx, v1 - hy);
                    }
                } else {
                    const size_t off = (size_t)grow * KN_ + (head - NH_ - NKV_) * HD_ + c;
                    *(__half2*)(Vhi + off) = __floats2half2_rn(v0, v1);
                }
            }
        }
    }
}

// ---------------------------------------------------------------------------
// Tensor-core flash attention: BQ=128 (8 warps, 256 threads), BK=64.
// QK 3-MMA (Q,K hi/lo), PV 1-MMA. Same per-query math as R12 -> bit-identical.
// ---------------------------------------------------------------------------
#define BQ 128
#define BK 64
#define AT_THREADS 256
#define KSTR 136
#define ABUF (BK * KSTR * 2)
#define ATT_SMEM (3 * ABUF)          // Khi, Klo, Vhi = 52224 B

__global__ __launch_bounds__(AT_THREADS)
void attn_mma(const __half* __restrict__ Qhi, const __half* __restrict__ Qlo,
              const __half* __restrict__ Khi, const __half* __restrict__ Klo,
              const __half* __restrict__ Vhi,
              __half* __restrict__ AOh)
{
    extern __shared__ char smraw[];
    __half* sKhi = (__half*)(smraw);
    __half* sKlo = (__half*)(smraw + ABUF);
    __half* sVhi = (__half*)(smraw + 2 * ABUF);

    const int qt = blockIdx.x, h = blockIdx.y, b = blockIdx.z;
    const int q0 = qt * BQ;
    const int kvh = h >> 2;
    const int tid = threadIdx.x;
    const int w = tid >> 5, lane = tid & 31;
    const int lr = lane >> 2, lc = lane & 3;

    const int qrow0 = q0 + w * 16 + lr;
    const int qrow1 = qrow0 + 8;

    // Q fragments: direct fp16 hi/lo loads from global
    unsigned qa_hi[8][4], qa_lo[8][4];
    {
        const size_t o0 = ((size_t)(b * S_) + qrow0) * QN_ + h * HD_;
        const size_t o1 = ((size_t)(b * S_) + qrow1) * QN_ + h * HD_;
#pragma unroll
        for (int kt = 0; kt < 8; kt++) {
            const int c0 = kt * 16 + 2 * lc;
            qa_hi[kt][0] = *(const unsigned*)(Qhi + o0 + c0);
            qa_hi[kt][1] = *(const unsigned*)(Qhi + o1 + c0);
            qa_hi[kt][2] = *(const unsigned*)(Qhi + o0 + c0 + 8);
            qa_hi[kt][3] = *(const unsigned*)(Qhi + o1 + c0 + 8);
            qa_lo[kt][0] = *(const unsigned*)(Qlo + o0 + c0);
            qa_lo[kt][1] = *(const unsigned*)(Qlo + o1 + c0);
            qa_lo[kt][2] = *(const unsigned*)(Qlo + o0 + c0 + 8);
            qa_lo[kt][3] = *(const unsigned*)(Qlo + o1 + c0 + 8);
        }
    }

    float m0 = -1e30f, m1 = -1e30f, l0 = 0.f, l1 = 0.f;
    float o[16][4];
#pragma unroll
    for (int i = 0; i < 16; i++)
#pragma unroll
        for (int j = 0; j < 4; j++) o[i][j] = 0.f;

    const int nTiles = (q0 + BQ) / BK;     // = 2*qt + 2
    const int wEnd = q0 + w * 16 + 16;
    const int ldr = (lane & 7) + ((lane >> 3) & 1) * 8;
    const int ldc = ((lane >> 4) & 1) * 8;
    const int klr = lane & 7;
    const int kmg = lane >> 3;

    const size_t kv_base = (size_t)(b * S_) * KN_ + kvh * HD_;

    auto load_k = [&](int kbase) {
        const size_t off = kv_base + (size_t)kbase * KN_;
#pragma unroll
        for (int j = 0; j < 4; j++) {
            const int idx = tid + AT_THREADS * j;   // 0..1023
            const int row = idx >> 4, c16 = idx & 15;
            const size_t g = off + (size_t)row * KN_ + c16 * 8;
            cp_async16(sKhi + row * KSTR + c16 * 8, Khi + g);
            cp_async16(sKlo + row * KSTR + c16 * 8, Klo + g);
        }
        asm volatile("cp.async.commit_group;");
    };
    auto load_v = [&](int kbase) {
        const size_t off = kv_base + (size_t)kbase * KN_;
#pragma unroll
        for (int j = 0; j < 4; j++) {
            const int idx = tid + AT_THREADS * j;
            const int row = idx >> 4, c16 = idx & 15;
            cp_async16(sVhi + row * KSTR + c16 * 8, Vhi + off + (size_t)row * KN_ + c16 * 8);
        }
        asm volatile("cp.async.commit_group;");
    };

    load_k(0);
    asm volatile("cp.async.wait_group 0;");
    __syncthreads();

    for (int kt = 0; kt < nTiles; kt++) {
        const int kbase = kt * BK;
        const bool active = kbase < wEnd;

        load_v(kbase);   // overlaps QK compute

        float sA[8][4];
        unsigned pa[4][4];

        if (active) {
#pragma unroll
            for (int nt = 0; nt < 8; nt++)
#pragma unroll
                for (int j = 0; j < 4; j++) sA[nt][j] = 0.f;

#pragma unroll
            for (int dkt2 = 0; dkt2 < 4; dkt2++) {
                const int col = dkt2 * 32 + kmg * 8;
#pragma unroll
                for (int nt = 0; nt < 8; nt++) {
                    unsigned bh[4], bl[4];
                    ldsm4(bh, sKhi + (nt * 8 + klr) * KSTR + col);
                    ldsm4(bl, sKlo + (nt * 8 + klr) * KSTR + col);
                    mma_fp16(sA[nt], qa_hi[2 * dkt2],     bh[0], bh[1]);
                    mma_fp16(sA[nt], qa_hi[2 * dkt2],     bl[0], bl[1]);
                    mma_fp16(sA[nt], qa_lo[2 * dkt2],     bh[0], bh[1]);
                    mma_fp16(sA[nt], qa_hi[2 * dkt2 + 1], bh[2], bh[3]);
                    mma_fp16(sA[nt], qa_hi[2 * dkt2 + 1], bl[2], bl[3]);
                    mma_fp16(sA[nt], qa_lo[2 * dkt2 + 1], bh[2], bh[3]);
                }
            }

            if (kbase + BK > qrow0) {
#pragma unroll
                for (int nt = 0; nt < 8; nt++) {
                    const int j0 = kbase + nt * 8 + 2 * lc;
                    if (j0 > qrow0)     sA[nt][0] = -1e30f;
                    if (j0 + 1 > qrow0) sA[nt][1] = -1e30f;
                    if (j0 > qrow1)     sA[nt][2] = -1e30f;
                    if (j0 + 1 > qrow1) sA[nt][3] = -1e30f;
                }
            }

            float mt0 = -1e30f, mt1 = -1e30f;
#pragma unroll
            for (int nt = 0; nt < 8; nt++) {
                mt0 = fmaxf(mt0, fmaxf(sA[nt][0], sA[nt][1]));
                mt1 = fmaxf(mt1, fmaxf(sA[nt][2], sA[nt][3]));
            }
            mt0 = fmaxf(mt0, __shfl_xor_sync(0xffffffffu, mt0, 1));
            mt0 = fmaxf(mt0, __shfl_xor_sync(0xffffffffu, mt0, 2));
            mt1 = fmaxf(mt1, __shfl_xor_sync(0xffffffffu, mt1, 1));
            mt1 = fmaxf(mt1, __shfl_xor_sync(0xffffffffu, mt1, 2));

            const float nm0 = fmaxf(m0, mt0);
            const float nm1 = fmaxf(m1, mt1);
            const float al0 = __expf(m0 - nm0);
            const float al1 = __expf(m1 - nm1);

            float rs0 = 0.f, rs1 = 0.f;
#pragma unroll
            for (int nt = 0; nt < 8; nt++) {
                sA[nt][0] = __expf(sA[nt][0] - nm0);
                sA[nt][1] = __expf(sA[nt][1] - nm0);
                sA[nt][2] = __expf(sA[nt][2] - nm1);
                sA[nt][3] = __expf(sA[nt][3] - nm1);
                rs0 += sA[nt][0] + sA[nt][1];
                rs1 += sA[nt][2] + sA[nt][3];
            }
            rs0 += __shfl_xor_sync(0xffffffffu, rs0, 1);
            rs0 += __shfl_xor_sync(0xffffffffu, rs0, 2);
            rs1 += __shfl_xor_sync(0xffffffffu, rs1, 1);
            rs1 += __shfl_xor_sync(0xffffffffu, rs1, 2);

            l0 = l0 * al0 + rs0;
            l1 = l1 * al1 + rs1;
            m0 = nm0; m1 = nm1;

#pragma unroll
            for (int i = 0; i < 16; i++) {
                o[i][0] *= al0; o[i][1] *= al0;
                o[i][2] *= al1; o[i][3] *= al1;
            }

#pragma unroll
            for (int t = 0; t < 4; t++) {
                __half2 p0 = __floats2half2_rn(sA[2 * t][0],     sA[2 * t][1]);
                __half2 p1 = __floats2half2_rn(sA[2 * t][2],     sA[2 * t][3]);
                __half2 p2 = __floats2half2_rn(sA[2 * t + 1][0], sA[2 * t + 1][1]);
                __half2 p3 = __floats2half2_rn(sA[2 * t + 1][2], sA[2 * t + 1][3]);
                pa[t][0] = *(unsigned*)&p0;
                pa[t][1] = *(unsigned*)&p1;
                pa[t][2] = *(unsigned*)&p2;
                pa[t][3] = *(unsigned*)&p3;
            }
        }

        asm volatile("cp.async.wait_group 0;");
        __syncthreads();

        if (kt + 1 < nTiles) load_k(kbase + BK);   // overlaps PV compute

        if (active) {
#pragma unroll
            for (int t = 0; t < 4; t++) {
#pragma unroll
                for (int np = 0; np < 8; np++) {
                    unsigned vh[4];
                    ldsm4t(vh, sVhi + (t * 16 + ldr) * KSTR + np * 16 + ldc);
                    mma_fp16(o[2 * np],     pa[t], vh[0], vh[1]);
                    mma_fp16(o[2 * np + 1], pa[t], vh[2], vh[3]);
                }
            }
        }

        asm volatile("cp.async.wait_group 0;");
        __syncthreads();
    }

    // epilogue: normalize + fp16 (feeds fp16 O-GEMM)
    const float il0 = 1.f / l0;
    const float il1 = 1.f / l1;
    __half* O0 = AOh + ((size_t)(b * S_) + qrow0) * QN_ + h * HD_;
    __half* O1 = AOh + ((size_t)(b * S_) + qrow1) * QN_ + h * HD_;
#pragma unroll
    for (int nt = 0; nt < 16; nt++) {
        *(__half2*)(O0 + nt * 8 + 2 * lc) =
            __floats2half2_rn(o[nt][0] * il0, o[nt][1] * il0);
        *(__half2*)(O1 + nt * 8 + 2 * lc) =
            __floats2half2_rn(o[nt][2] * il1, o[nt][3] * il1);
    }
}

// ---------------------------------------------------------------------------
// Launcher
// ---------------------------------------------------------------------------
extern "C" void kernel_launch(void* const* d_in, const int* in_sizes, int n_in,
                              void* d_out, int out_size)
{
    const float* X   = (const float*)d_in[0];
    const int*   pos = (const int*)  d_in[1];
    const float* Wq  = (const float*)d_in[2];
    const float* bq  = (const float*)d_in[3];
    const float* Wk  = (const float*)d_in[4];
    const float* bk  = (const float*)d_in[5];
    const float* Wv  = (const float*)d_in[6];
    const float* bv  = (const float*)d_in[7];
    const float* Wo  = (const float*)d_in[8];
    float* out = (float*)d_out;

    __half *Xh, *Wqkvh, *Woh, *AOh, *Qhi, *Qlo, *Khi, *Klo, *Vhi;
    float *bqkv;
    cudaGetSymbolAddress((void**)&Xh,    g_Xh);
    cudaGetSymbolAddress((void**)&Wqkvh, g_Wqkvh);
    cudaGetSymbolAddress((void**)&bqkv,  g_bqkv);
    cudaGetSymbolAddress((void**)&Woh,   g_Woh);
    cudaGetSymbolAddress((void**)&AOh,   g_AOh);
    cudaGetSymbolAddress((void**)&Qhi,   g_Qhi);
    cudaGetSymbolAddress((void**)&Qlo,   g_Qlo);
    cudaGetSymbolAddress((void**)&Khi,   g_Khi);
    cudaGetSymbolAddress((void**)&Klo,   g_Klo);
    cudaGetSymbolAddress((void**)&Vhi,   g_Vhi);

    cudaFuncSetAttribute(attn_mma,      cudaFuncAttributeMaxDynamicSharedMemorySize, ATT_SMEM);
    cudaFuncSetAttribute(gemm_fp16,     cudaFuncAttributeMaxDynamicSharedMemorySize, G_SMEM);
    cudaFuncSetAttribute(gemm_qkv_rope, cudaFuncAttributeMaxDynamicSharedMemorySize, QKV_SMEM);

    // Fused prep (fp16 rounding + concat + bias)
    prep_all<<<1184, 256>>>(X, Wq, Wk, Wv, Wo, bq, bk, bv, Xh, Wqkvh, Woh, bqkv);

    // Fused QKV projection + RoPE + fp16 splits
    gemm_qkv_rope<<<dim3(QKV_N / 128, M_ / 128), 256, QKV_SMEM>>>(
        Xh, Wqkvh, bqkv, pos, Qhi, Qlo, Khi, Klo, Vhi);

    // Attention (QK 3-MMA, PV 1-MMA), BQ=128, writes fp16 AO
    attn_mma<<<dim3(S_ / BQ, NH_, B_), AT_THREADS, ATT_SMEM>>>(
        Qhi, Qlo, Khi, Klo, Vhi, AOh);

    // Output projection (fp16 tensor cores)
    gemm_fp16<<<dim3(QN_ / 128, M_ / 128), 256, G_SMEM>>>(
        AOh, Woh, nullptr, out, M_, QN_, H_);
}

// round 15
// speedup vs baseline: 1.0808x; 1.0398x over previous
#include <cuda_runtime.h>
#include <cuda_bf16.h>
#include <cuda_fp16.h>
#include <math.h>
#include <stdint.h>

// Problem constants
#define B_  2
#define S_  2048
#define H_  4096
#define NH_ 32
#define NKV_ 8
#define HD_ 128
#define M_  (B_ * S_)          // 4096 rows
#define QN_ (NH_ * HD_)        // 4096
#define KN_ (NKV_ * HD_)       // 1024
#define QKV_N (QN_ + 2 * KN_)  // 6144

// Scratch (device globals; no allocations allowed)
__device__ __half g_Xh[M_ * H_];
__device__ __half g_Wqkvh[H_ * QKV_N];
__device__ float  g_bqkv[QKV_N];
__device__ __half g_Woh[QN_ * H_];
__device__ __half g_AOh[M_ * QN_];
__device__ __half g_Qhi[M_ * QN_], g_Qlo[M_ * QN_];
__device__ __half g_Khi[M_ * KN_], g_Klo[M_ * KN_];
__device__ __half g_Vhi[M_ * KN_];

__device__ __forceinline__ void st_half4(__half* p, float4 v)
{
    *(__half2*)(p)     = __floats2half2_rn(v.x, v.y);
    *(__half2*)(p + 2) = __floats2half2_rn(v.z, v.w);
}

// ---------------------------------------------------------------------------
// Fused prep (R12, unchanged)
// ---------------------------------------------------------------------------
#define SEG0 (M_ * H_ / 4)
#define SEG1 (H_ * QKV_N / 4)
#define SEG2 (QN_ * H_ / 4)
#define SEG3 (QKV_N / 4)
#define SEG_TOTAL (SEG0 + SEG1 + SEG2 + SEG3)

__global__ __launch_bounds__(256)
void prep_all(const float* __restrict__ X,
              const float* __restrict__ Wq, const float* __restrict__ Wk,
              const float* __restrict__ Wv, const float* __restrict__ Wo,
              const float* __restrict__ bq, const float* __restrict__ bk,
              const float* __restrict__ bv,
              __half* __restrict__ Xh, __half* __restrict__ Wqkvh,
              __half* __restrict__ Woh, float* __restrict__ bqkv)
{
    const int stride = gridDim.x * 256;
    for (int u = blockIdx.x * 256 + threadIdx.x; u < SEG_TOTAL; u += stride) {
        if (u < SEG0) {
            st_half4(Xh + (size_t)u * 4, *(const float4*)(X + (size_t)u * 4));
        } else if (u < SEG0 + SEG1) {
            const int j = u - SEG0;
            const int row = j / (QKV_N / 4);
            const int c = (j - row * (QKV_N / 4)) * 4;
            float4 v;
            if (c < QN_)
                v = *(const float4*)(Wq + (size_t)row * QN_ + c);
            else if (c < QN_ + KN_)
                v = *(const float4*)(Wk + (size_t)row * KN_ + (c - QN_));
            else
                v = *(const float4*)(Wv + (size_t)row * KN_ + (c - QN_ - KN_));
            st_half4(Wqkvh + (size_t)row * QKV_N + c, v);
        } else if (u < SEG0 + SEG1 + SEG2) {
            const int j = u - SEG0 - SEG1;
            st_half4(Woh + (size_t)j * 4, *(const float4*)(Wo + (size_t)j * 4));
        } else {
            const int j = u - SEG0 - SEG1 - SEG2;
            const int c = j * 4;
            float4 v;
            if (c < QN_)            v = *(const float4*)(bq + c);
            else if (c < QN_ + KN_) v = *(const float4*)(bk + c - QN_);
            else                    v = *(const float4*)(bv + c - QN_ - KN_);
            *(float4*)(bqkv + c) = v;
        }
    }
}

// ---------------------------------------------------------------------------
// Shared MMA / ldmatrix helpers
// ---------------------------------------------------------------------------
__device__ __forceinline__ void cp_async16(void* smem_dst, const void* gsrc) {
    unsigned dst = (unsigned)__cvta_generic_to_shared(smem_dst);
    asm volatile("cp.async.cg.shared.global [%0], [%1], 16;" :: "r"(dst), "l"(gsrc));
}

__device__ __forceinline__ void ldsm4(unsigned r[4], const void* p)
{
    unsigned a = (unsigned)__cvta_generic_to_shared(p);
    asm volatile(
        "ldmatrix.sync.aligned.m8n8.x4.shared.b16 {%0,%1,%2,%3}, [%4];"
        : "=r"(r[0]), "=r"(r[1]), "=r"(r[2]), "=r"(r[3]) : "r"(a));
}

__device__ __forceinline__ void ldsm4t(unsigned r[4], const void* p)
{
    unsigned a = (unsigned)__cvta_generic_to_shared(p);
    asm volatile(
        "ldmatrix.sync.aligned.m8n8.x4.trans.shared.b16 {%0,%1,%2,%3}, [%4];"
        : "=r"(r[0]), "=r"(r[1]), "=r"(r[2]), "=r"(r[3]) : "r"(a));
}

__device__ __forceinline__ void mma_fp16(float c[4], const unsigned a[4],
                                         unsigned b0, unsigned b1)
{
    asm volatile(
        "mma.sync.aligned.m16n8k16.row.col.f32.f16.f16.f32 "
        "{%0,%1,%2,%3}, {%4,%5,%6,%7}, {%8,%9}, {%0,%1,%2,%3};"
        : "+f"(c[0]), "+f"(c[1]), "+f"(c[2]), "+f"(c[3])
        : "r"(a[0]), "r"(a[1]), "r"(a[2]), "r"(a[3]), "r"(b0), "r"(b1));
}

// ---------------------------------------------------------------------------
// GEMM tiling constants (128x128, BK=32, 3-stage) — R12 mainloop
// ---------------------------------------------------------------------------
#define FA_STR 40
#define FB_STR 136
#define FSTG (128 * FA_STR + 32 * FB_STR)
#define G_SMEM (3 * FSTG * 2)
#define TSTR 132
#define QKV_SMEM (128 * TSTR * 4)

// ---------------------------------------------------------------------------
// Plain FP16 GEMM (O projection): R12 version, untouched.
// ---------------------------------------------------------------------------
__global__ __launch_bounds__(256)
void gemm_fp16(const __half* __restrict__ A, const __half* __restrict__ B,
               const float* __restrict__ bias, float* __restrict__ C,
               int M, int N, int K)
{
    extern __shared__ __half gsm[];

    const int tid  = threadIdx.x;
    const int wid  = tid >> 5;
    const int lane = tid & 31;
    const int warp_m = (wid & 1) * 64;
    const int warp_n = (wid >> 1) * 32;
    const int brow = blockIdx.y * 128;
    const int bcol = blockIdx.x * 128;
    const int lr = lane >> 2;
    const int lc = lane & 3;
    const int ldr  = (lane & 7) + ((lane >> 3) & 1) * 8;
    const int ldc8 = ((lane >> 4) & 1) * 8;

    float acc[4][4][4];
#pragma unroll
    for (int mt = 0; mt < 4; mt++)
#pragma unroll
        for (int nt = 0; nt < 4; nt++)
#pragma unroll
            for (int i = 0; i < 4; i++) acc[mt][nt][i] = 0.f;

    auto load_stage = [&](int s, int k0) {
        __half* As = gsm + s * FSTG;
        __half* Bs = As + 128 * FA_STR;
#pragma unroll
        for (int it = 0; it < 2; it++) {
            const int idx = tid + 256 * it;
            const int r = idx >> 2, c = (idx & 3) * 8;
            cp_async16(&As[r * FA_STR + c], &A[(size_t)(brow + r) * K + k0 + c]);
        }
#pragma unroll
        for (int it = 0; it < 2; it++) {
            const int idx = tid + 256 * it;
            const int r = idx >> 4, c = (idx & 15) * 8;
            cp_async16(&Bs[r * FB_STR + c], &B[(size_t)(k0 + r) * N + bcol + c]);
        }
        asm volatile("cp.async.commit_group;");
    };

    const int KT = K / 32;
    load_stage(0, 0);
    load_stage(1, 32);

    for (int kt = 0; kt < KT; kt++) {
        const int s = kt % 3;
        if (kt + 1 < KT) asm volatile("cp.async.wait_group 1;");
        else             asm volatile("cp.async.wait_group 0;");
        __syncthreads();

        if (kt + 2 < KT) load_stage((kt + 2) % 3, (kt + 2) * 32);

        const __half* As = gsm + s * FSTG;
        const __half* Bs = As + 128 * FA_STR;

#pragma unroll
        for (int ks = 0; ks < 2; ks++) {
            unsigned af[4][4];
#pragma unroll
            for (int mt = 0; mt < 4; mt++)
                ldsm4(af[mt], As + (warp_m + mt * 16 + ldr) * FA_STR + ks * 16 + ldc8);

            unsigned bf[4][2];
#pragma unroll
            for (int nt2 = 0; nt2 < 2; nt2++) {
                unsigned t4[4];
                ldsm4t(t4, Bs + (ks * 16 + ldr) * FB_STR + warp_n + nt2 * 16 + ldc8);
                bf[2 * nt2][0]     = t4[0];
                bf[2 * nt2][1]     = t4[1];
                bf[2 * nt2 + 1][0] = t4[2];
                bf[2 * nt2 + 1][1] = t4[3];
            }

#pragma unroll
            for (int mt = 0; mt < 4; mt++)
#pragma unroll
                for (int nt = 0; nt < 4; nt++)
                    mma_fp16(acc[mt][nt], af[mt], bf[nt][0], bf[nt][1]);
        }
    }

#pragma unroll
    for (int mt = 0; mt < 4; mt++) {
#pragma unroll
        for (int nt = 0; nt < 4; nt++) {
            const int row0 = brow + warp_m + mt * 16 + lr;
            const int col  = bcol + warp_n + nt * 8 + lc * 2;
            const float b0 = bias ? bias[col]     : 0.f;
            const float b1 = bias ? bias[col + 1] : 0.f;
            float2 v0 = make_float2(acc[mt][nt][0] + b0, acc[mt][nt][1] + b1);
            float2 v1 = make_float2(acc[mt][nt][2] + b0, acc[mt][nt][3] + b1);
            *(float2*)&C[(size_t)row0 * N + col]       = v0;
            *(float2*)&C[(size_t)(row0 + 8) * N + col] = v1;
        }
    }
}

// ---------------------------------------------------------------------------
// QKV GEMM with fused RoPE epilogue (R12 version, untouched).
// ---------------------------------------------------------------------------
__global__ __launch_bounds__(256)
void gemm_qkv_rope(const __half* __restrict__ A, const __half* __restrict__ B,
                   const float* __restrict__ bias, const int* __restrict__ pos_ids,
                   __half* __restrict__ Qhi, __half* __restrict__ Qlo,
                   __half* __restrict__ Khi, __half* __restrict__ Klo,
                   __half* __restrict__ Vhi)
{
    extern __shared__ __half gsm[];
    const int N = QKV_N, K = H_;

    const int tid  = threadIdx.x;
    const int wid  = tid >> 5;
    const int lane = tid & 31;
    const int warp_m = (wid & 1) * 64;
    const int warp_n = (wid >> 1) * 32;
    const int brow = blockIdx.y * 128;
    const int bcol = blockIdx.x * 128;
    const int lr = lane >> 2;
    const int lc = lane & 3;
    const int ldr  = (lane & 7) + ((lane >> 3) & 1) * 8;
    const int ldc8 = ((lane >> 4) & 1) * 8;

    float acc[4][4][4];
#pragma unroll
    for (int mt = 0; mt < 4; mt++)
#pragma unroll
        for (int nt = 0; nt < 4; nt++)
#pragma unroll
            for (int i = 0; i < 4; i++) acc[mt][nt][i] = 0.f;

    auto load_stage = [&](int s, int k0) {
        __half* As = gsm + s * FSTG;
        __half* Bs = As + 128 * FA_STR;
#pragma unroll
        for (int it = 0; it < 2; it++) {
            const int idx = tid + 256 * it;
            const int r = idx >> 2, c = (idx & 3) * 8;
            cp_async16(&As[r * FA_STR + c], &A[(size_t)(brow + r) * K + k0 + c]);
        }
#pragma unroll
        for (int it = 0; it < 2; it++) {
            const int idx = tid + 256 * it;
            const int r = idx >> 4, c = (idx & 15) * 8;
            cp_async16(&Bs[r * FB_STR + c], &B[(size_t)(k0 + r) * N + bcol + c]);
        }
        asm volatile("cp.async.commit_group;");
    };

    const int KT = K / 32;
    load_stage(0, 0);
    load_stage(1, 32);

    for (int kt = 0; kt < KT; kt++) {
        const int s = kt % 3;
        if (kt + 1 < KT) asm volatile("cp.async.wait_group 1;");
        else             asm volatile("cp.async.wait_group 0;");
        __syncthreads();

        if (kt + 2 < KT) load_stage((kt + 2) % 3, (kt + 2) * 32);

        const __half* As = gsm + s * FSTG;
        const __half* Bs = As + 128 * FA_STR;

#pragma unroll
        for (int ks = 0; ks < 2; ks++) {
            unsigned af[4][4];
#pragma unroll
            for (int mt = 0; mt < 4; mt++)
                ldsm4(af[mt], As + (warp_m + mt * 16 + ldr) * FA_STR + ks * 16 + ldc8);

            unsigned bf[4][2];
#pragma unroll
            for (int nt2 = 0; nt2 < 2; nt2++) {
                unsigned t4[4];
                ldsm4t(t4, Bs + (ks * 16 + ldr) * FB_STR + warp_n + nt2 * 16 + ldc8);
                bf[2 * nt2][0]     = t4[0];
                bf[2 * nt2][1]     = t4[1];
                bf[2 * nt2 + 1][0] = t4[2];
                bf[2 * nt2 + 1][1] = t4[3];
            }

#pragma unroll
            for (int mt = 0; mt < 4; mt++)
#pragma unroll
                for (int nt = 0; nt < 4; nt++)
                    mma_fp16(acc[mt][nt], af[mt], bf[nt][0], bf[nt][1]);
        }
    }

    // ---- epilogue: stage acc+bias in smem fp32, then rope + fp16 split ----
    __syncthreads();
    float* tile = reinterpret_cast<float*>(gsm);

#pragma unroll
    for (int mt = 0; mt < 4; mt++) {
#pragma unroll
        for (int nt = 0; nt < 4; nt++) {
            const int r0 = warp_m + mt * 16 + lr;
            const int c  = warp_n + nt * 8 + lc * 2;
            const float b0 = bias[bcol + c];
            const float b1 = bias[bcol + c + 1];
            tile[r0 * TSTR + c]           = acc[mt][nt][0] + b0;
            tile[r0 * TSTR + c + 1]       = acc[mt][nt][1] + b1;
            tile[(r0 + 8) * TSTR + c]     = acc[mt][nt][2] + b0;
            tile[(r0 + 8) * TSTR + c + 1] = acc[mt][nt][3] + b1;
        }
    }
    __syncthreads();

    const int head = blockIdx.x;

#pragma unroll
    for (int mt = 0; mt < 4; mt++) {
#pragma unroll
        for (int rr = 0; rr < 2; rr++) {
            const int rl = warp_m + mt * 16 + lr + rr * 8;
            const int grow = brow + rl;
            const int pos = pos_ids[grow];

#pragma unroll
            for (int nt = 0; nt < 4; nt++) {
                const int c = warp_n + nt * 8 + lc * 2;
                float v0 = tile[rl * TSTR + c];
                float v1 = tile[rl * TSTR + c + 1];

                if (head < NH_ + NKV_) {
                    const int poff = (c < 64) ? 64 : -64;
                    const float sgn = (c < 64) ? -1.f : 1.f;
                    const float o0 = sgn * tile[rl * TSTR + c + poff];
                    const float o1 = sgn * tile[rl * TSTR + c + 1 + poff];

                    const int i0 = c & 63, i1 = (c + 1) & 63;
                    float c0, s0, c1, s1;
                    {
                        const float f0 = exp2f(-(float)(2 * i0) * (1.0f / 128.0f) * 13.28771238f);
                        sincosf((float)pos * f0, &s0, &c0);
                        const float f1 = exp2f(-(float)(2 * i1) * (1.0f / 128.0f) * 13.28771238f);
                        sincosf((float)pos * f1, &s1, &c1);
                    }
                    v0 = v0 * c0 + o0 * s0;
                    v1 = v1 * c1 + o1 * s1;

                    if (head < NH_) {
                        v0 *= 0.08838834764831845f;
                        v1 *= 0.08838834764831845f;
                        const size_t off = (size_t)grow * QN_ + head * HD_ + c;
                        __half2 h = __floats2half2_rn(v0, v1);
                        float hx = __low2float(h), hy = __high2float(h);
                        *(__half2*)(Qhi + off) = h;
                        *(__half2*)(Qlo + off) = __floats2half2_rn(v0 - hx, v1 - hy);
                    } else {
                        const size_t off = (size_t)grow * KN_ + (head - NH_) * HD_ + c;
                        __half2 h = __floats2half2_rn(v0, v1);
                        float hx = __low2float(h), hy = __high2float(h);
                        *(__half2*)(Khi + off) = h;
                        *(__half2*)(Klo + off) = __floats2half2_rn(v0 - hx, v1 - hy);
                    }
                } else {
                    const size_t off = (size_t)grow * KN_ + (head - NH_ - NKV_) * HD_ + c;
                    *(__half2*)(Vhi + off) = __floats2half2_rn(v0, v1);
                }
            }
        }
    }
}

// ---------------------------------------------------------------------------
// Tensor-core flash attention: BQ=64, double-buffered K+V (one wait + one
// sync per tile; prefetch overlaps full QK+softmax+PV). Bit-identical math.
// ---------------------------------------------------------------------------
#define BQ 64
#define BK 64
#define KSTR 136
#define ABUF (BK * KSTR * 2)
#define ASTG (3 * ABUF)              // Khi, Klo, Vhi per buffer
#define ATT_SMEM (2 * ASTG)          // 104448 B

__global__ __launch_bounds__(128)
void attn_mma(const __half* __restrict__ Qhi, const __half* __restrict__ Qlo,
              const __half* __restrict__ Khi, const __half* __restrict__ Klo,
              const __half* __restrict__ Vhi,
              __half* __restrict__ AOh)
{
    extern __shared__ char smraw[];

    const int qt = blockIdx.x, h = blockIdx.y, b = blockIdx.z;
    const int q0 = qt * BQ;
    const int kvh = h >> 2;
    const int tid = threadIdx.x;
    const int w = tid >> 5, lane = tid & 31;
    const int lr = lane >> 2, lc = lane & 3;

    const int qrow0 = q0 + w * 16 + lr;
    const int qrow1 = qrow0 + 8;

    // Q fragments: direct fp16 hi/lo loads from global
    unsigned qa_hi[8][4], qa_lo[8][4];
    {
        const size_t o0 = ((size_t)(b * S_) + qrow0) * QN_ + h * HD_;
        const size_t o1 = ((size_t)(b * S_) + qrow1) * QN_ + h * HD_;
#pragma unroll
        for (int kt = 0; kt < 8; kt++) {
            const int c0 = kt * 16 + 2 * lc;
            qa_hi[kt][0] = *(const unsigned*)(Qhi + o0 + c0);
            qa_hi[kt][1] = *(const unsigned*)(Qhi + o1 + c0);
            qa_hi[kt][2] = *(const unsigned*)(Qhi + o0 + c0 + 8);
            qa_hi[kt][3] = *(const unsigned*)(Qhi + o1 + c0 + 8);
            qa_lo[kt][0] = *(const unsigned*)(Qlo + o0 + c0);
            qa_lo[kt][1] = *(const unsigned*)(Qlo + o1 + c0);
            qa_lo[kt][2] = *(const unsigned*)(Qlo + o0 + c0 + 8);
            qa_lo[kt][3] = *(const unsigned*)(Qlo + o1 + c0 + 8);
        }
    }

    float m0 = -1e30f, m1 = -1e30f, l0 = 0.f, l1 = 0.f;
    float o[16][4];
#pragma unroll
    for (int i = 0; i < 16; i++)
#pragma unroll
        for (int j = 0; j < 4; j++) o[i][j] = 0.f;

    const int nTiles = qt + 1;
    const int wEnd = q0 + w * 16 + 16;
    const int ldr = (lane & 7) + ((lane >> 3) & 1) * 8;
    const int ldc = ((lane >> 4) & 1) * 8;
    const int klr = lane & 7;
    const int kmg = lane >> 3;

    const size_t kv_base = (size_t)(b * S_) * KN_ + kvh * HD_;

    // load K(hi,lo)+V for one tile into buffer s; single commit group
    auto load_kv = [&](int s, int kbase) {
        __half* dK = (__half*)(smraw + s * ASTG);
        __half* dKl = dK + ABUF / 2;              // note: ABUF bytes per plane
        __half* dV = (__half*)(smraw + s * ASTG + 2 * ABUF);
        // recompute as byte-based to avoid confusion:
        dK  = (__half*)(smraw + s * ASTG);
        dKl = (__half*)(smraw + s * ASTG + ABUF);
        const size_t off = kv_base + (size_t)kbase * KN_;
#pragma unroll
        for (int j = 0; j < 8; j++) {
            const int idx = tid + 128 * j;        // 0..1023
            const int row = idx >> 4, c16 = idx & 15;
            const size_t g = off + (size_t)row * KN_ + c16 * 8;
            cp_async16(dK  + row * KSTR + c16 * 8, Khi + g);
            cp_async16(dKl + row * KSTR + c16 * 8, Klo + g);
            cp_async16(dV  + row * KSTR + c16 * 8, Vhi + g);
        }
        asm volatile("cp.async.commit_group;");
    };

    load_kv(0, 0);

    for (int kt = 0; kt < nTiles; kt++) {
        const int s = kt & 1;
        const int kbase = kt * BK;
        const bool active = kbase < wEnd;

        asm volatile("cp.async.wait_group 0;");
        __syncthreads();

        if (kt + 1 < nTiles) load_kv(s ^ 1, kbase + BK);   // overlaps everything below

        const __half* sKhi = (const __half*)(smraw + s * ASTG);
        const __half* sKlo = (const __half*)(smraw + s * ASTG + ABUF);
        const __half* sVhi = (const __half*)(smraw + s * ASTG + 2 * ABUF);

        if (active) {
            float sA[8][4];
            unsigned pa[4][4];

#pragma unroll
            for (int nt = 0; nt < 8; nt++)
#pragma unroll
                for (int j = 0; j < 4; j++) sA[nt][j] = 0.f;

#pragma unroll
            for (int dkt2 = 0; dkt2 < 4; dkt2++) {
                const int col = dkt2 * 32 + kmg * 8;
#pragma unroll
                for (int nt = 0; nt < 8; nt++) {
                    unsigned bh[4], bl[4];
                    ldsm4(bh, sKhi + (nt * 8 + klr) * KSTR + col);
                    ldsm4(bl, sKlo + (nt * 8 + klr) * KSTR + col);
                    mma_fp16(sA[nt], qa_hi[2 * dkt2],     bh[0], bh[1]);
                    mma_fp16(sA[nt], qa_hi[2 * dkt2],     bl[0], bl[1]);
                    mma_fp16(sA[nt], qa_lo[2 * dkt2],     bh[0], bh[1]);
                    mma_fp16(sA[nt], qa_hi[2 * dkt2 + 1], bh[2], bh[3]);
                    mma_fp16(sA[nt], qa_hi[2 * dkt2 + 1], bl[2], bl[3]);
                    mma_fp16(sA[nt], qa_lo[2 * dkt2 + 1], bh[2], bh[3]);
                }
            }

            if (kbase + BK > qrow0) {
#pragma unroll
                for (int nt = 0; nt < 8; nt++) {
                    const int j0 = kbase + nt * 8 + 2 * lc;
                    if (j0 > qrow0)     sA[nt][0] = -1e30f;
                    if (j0 + 1 > qrow0) sA[nt][1] = -1e30f;
                    if (j0 > qrow1)     sA[nt][2] = -1e30f;
                    if (j0 + 1 > qrow1) sA[nt][3] = -1e30f;
                }
            }

            float mt0 = -1e30f, mt1 = -1e30f;
#pragma unroll
            for (int nt = 0; nt < 8; nt++) {
                mt0 = fmaxf(mt0, fmaxf(sA[nt][0], sA[nt][1]));
                mt1 = fmaxf(mt1, fmaxf(sA[nt][2], sA[nt][3]));
            }
            mt0 = fmaxf(mt0, __shfl_xor_sync(0xffffffffu, mt0, 1));
            mt0 = fmaxf(mt0, __shfl_xor_sync(0xffffffffu, mt0, 2));
            mt1 = fmaxf(mt1, __shfl_xor_sync(0xffffffffu, mt1, 1));
            mt1 = fmaxf(mt1, __shfl_xor_sync(0xffffffffu, mt1, 2));

            const float nm0 = fmaxf(m0, mt0);
            const float nm1 = fmaxf(m1, mt1);
            const float al0 = __expf(m0 - nm0);
            const float al1 = __expf(m1 - nm1);

            float rs0 = 0.f, rs1 = 0.f;
#pragma unroll
            for (int nt = 0; nt < 8; nt++) {
                sA[nt][0] = __expf(sA[nt][0] - nm0);
                sA[nt][1] = __expf(sA[nt][1] - nm0);
                sA[nt][2] = __expf(sA[nt][2] - nm1);
                sA[nt][3] = __expf(sA[nt][3] - nm1);
                rs0 += sA[nt][0] + sA[nt][1];
                rs1 += sA[nt][2] + sA[nt][3];
            }
            rs0 += __shfl_xor_sync(0xffffffffu, rs0, 1);
            rs0 += __shfl_xor_sync(0xffffffffu, rs0, 2);
            rs1 += __shfl_xor_sync(0xffffffffu, rs1, 1);
            rs1 += __shfl_xor_sync(0xffffffffu, rs1, 2);

            l0 = l0 * al0 + rs0;
            l1 = l1 * al1 + rs1;
            m0 = nm0; m1 = nm1;

#pragma unroll
            for (int i = 0; i < 16; i++) {
                o[i][0] *= al0; o[i][1] *= al0;
                o[i][2] *= al1; o[i][3] *= al1;
            }

#pragma unroll
            for (int t = 0; t < 4; t++) {
                __half2 p0 = __floats2half2_rn(sA[2 * t][0],     sA[2 * t][1]);
                __half2 p1 = __floats2half2_rn(sA[2 * t][2],     sA[2 * t][3]);
                __half2 p2 = __floats2half2_rn(sA[2 * t + 1][0], sA[2 * t + 1][1]);
                __half2 p3 = __floats2half2_rn(sA[2 * t + 1][2], sA[2 * t + 1][3]);
                pa[t][0] = *(unsigned*)&p0;
                pa[t][1] = *(unsigned*)&p1;
                pa[t][2] = *(unsigned*)&p2;
                pa[t][3] = *(unsigned*)&p3;
            }

#pragma unroll
            for (int t = 0; t < 4; t++) {
#pragma unroll
                for (int np = 0; np < 8; np++) {
                    unsigned vh[4];
                    ldsm4t(vh, sVhi + (t * 16 + ldr) * KSTR + np * 16 + ldc);
                    mma_fp16(o[2 * np],     pa[t], vh[0], vh[1]);
                    mma_fp16(o[2 * np + 1], pa[t], vh[2], vh[3]);
                }
            }
        }
    }

    // epilogue: normalize + fp16 (feeds fp16 O-GEMM)
    const float il0 = 1.f / l0;
    const float il1 = 1.f / l1;
    __half* O0 = AOh + ((size_t)(b * S_) + qrow0) * QN_ + h * HD_;
    __half* O1 = AOh + ((size_t)(b * S_) + qrow1) * QN_ + h * HD_;
#pragma unroll
    for (int nt = 0; nt < 16; nt++) {
        *(__half2*)(O0 + nt * 8 + 2 * lc) =
            __floats2half2_rn(o[nt][0] * il0, o[nt][1] * il0);
        *(__half2*)(O1 + nt * 8 + 2 * lc) =
            __floats2half2_rn(o[nt][2] * il1, o[nt][3] * il1);
    }
}

// ---------------------------------------------------------------------------
// Launcher
// ---------------------------------------------------------------------------
extern "C" void kernel_launch(void* const* d_in, const int* in_sizes, int n_in,
                              void* d_out, int out_size)
{
    const float* X   = (const float*)d_in[0];
    const int*   pos = (const int*)  d_in[1];
    const float* Wq  = (const float*)d_in[2];
    const float* bq  = (const float*)d_in[3];
    const float* Wk  = (const float*)d_in[4];
    const float* bk  = (const float*)d_in[5];
    const float* Wv  = (const float*)d_in[6];
    const float* bv  = (const float*)d_in[7];
    const float* Wo  = (const float*)d_in[8];
    float* out = (float*)d_out;

    __half *Xh, *Wqkvh, *Woh, *AOh, *Qhi, *Qlo, *Khi, *Klo, *Vhi;
    float *bqkv;
    cudaGetSymbolAddress((void**)&Xh,    g_Xh);
    cudaGetSymbolAddress((void**)&Wqkvh, g_Wqkvh);
    cudaGetSymbolAddress((void**)&bqkv,  g_bqkv);
    cudaGetSymbolAddress((void**)&Woh,   g_Woh);
    cudaGetSymbolAddress((void**)&AOh,   g_AOh);
    cudaGetSymbolAddress((void**)&Qhi,   g_Qhi);
    cudaGetSymbolAddress((void**)&Qlo,   g_Qlo);
    cudaGetSymbolAddress((void**)&Khi,   g_Khi);
    cudaGetSymbolAddress((void**)&Klo,   g_Klo);
    cudaGetSymbolAddress((void**)&Vhi,   g_Vhi);

    cudaFuncSetAttribute(attn_mma,      cudaFuncAttributeMaxDynamicSharedMemorySize, ATT_SMEM);
    cudaFuncSetAttribute(gemm_fp16,     cudaFuncAttributeMaxDynamicSharedMemorySize, G_SMEM);
    cudaFuncSetAttribute(gemm_qkv_rope, cudaFuncAttributeMaxDynamicSharedMemorySize, QKV_SMEM);

    // Fused prep (fp16 rounding + concat + bias)
    prep_all<<<1184, 256>>>(X, Wq, Wk, Wv, Wo, bq, bk, bv, Xh, Wqkvh, Woh, bqkv);

    // Fused QKV projection + RoPE + fp16 splits
    gemm_qkv_rope<<<dim3(QKV_N / 128, M_ / 128), 256, QKV_SMEM>>>(
        Xh, Wqkvh, bqkv, pos, Qhi, Qlo, Khi, Klo, Vhi);

    // Attention (QK 3-MMA, PV 1-MMA), double-buffered K+V, writes fp16 AO
    attn_mma<<<dim3(S_ / BQ, NH_, B_), 128, ATT_SMEM>>>(
        Qhi, Qlo, Khi, Klo, Vhi, AOh);

    // Output projection (fp16 tensor cores)
    gemm_fp16<<<dim3(QN_ / 128, M_ / 128), 256, G_SMEM>>>(
        AOh, Woh, nullptr, out, M_, QN_, H_);
}

// round 16
// speedup vs baseline: 1.1240x; 1.0399x over previous
#include <cuda_runtime.h>
#include <cuda_bf16.h>
#include <cuda_fp16.h>
#include <math.h>
#include <stdint.h>

// Problem constants
#define B_  2
#define S_  2048
#define H_  4096
#define NH_ 32
#define NKV_ 8
#define HD_ 128
#define M_  (B_ * S_)          // 4096 rows
#define QN_ (NH_ * HD_)        // 4096
#define KN_ (NKV_ * HD_)       // 1024
#define QKV_N (QN_ + 2 * KN_)  // 6144

// Scratch (device globals; no allocations allowed)
__device__ __half g_Xh[M_ * H_];
__device__ __half g_Wqkvh[H_ * QKV_N];
__device__ float  g_bqkv[QKV_N];
__device__ __half g_Woh[QN_ * H_];
__device__ __half g_AOh[M_ * QN_];
__device__ __half g_Qhi[M_ * QN_], g_Qlo[M_ * QN_];
__device__ __half g_Khi[M_ * KN_], g_Klo[M_ * KN_];
__device__ __half g_Vhi[M_ * KN_];

__device__ __forceinline__ void st_half4(__half* p, float4 v)
{
    *(__half2*)(p)     = __floats2half2_rn(v.x, v.y);
    *(__half2*)(p + 2) = __floats2half2_rn(v.z, v.w);
}

// ---------------------------------------------------------------------------
// Fused prep (unchanged)
// ---------------------------------------------------------------------------
#define SEG0 (M_ * H_ / 4)
#define SEG1 (H_ * QKV_N / 4)
#define SEG2 (QN_ * H_ / 4)
#define SEG3 (QKV_N / 4)
#define SEG_TOTAL (SEG0 + SEG1 + SEG2 + SEG3)

__global__ __launch_bounds__(256)
void prep_all(const float* __restrict__ X,
              const float* __restrict__ Wq, const float* __restrict__ Wk,
              const float* __restrict__ Wv, const float* __restrict__ Wo,
              const float* __restrict__ bq, const float* __restrict__ bk,
              const float* __restrict__ bv,
              __half* __restrict__ Xh, __half* __restrict__ Wqkvh,
              __half* __restrict__ Woh, float* __restrict__ bqkv)
{
    const int stride = gridDim.x * 256;
    for (int u = blockIdx.x * 256 + threadIdx.x; u < SEG_TOTAL; u += stride) {
        if (u < SEG0) {
            st_half4(Xh + (size_t)u * 4, *(const float4*)(X + (size_t)u * 4));
        } else if (u < SEG0 + SEG1) {
            const int j = u - SEG0;
            const int row = j / (QKV_N / 4);
            const int c = (j - row * (QKV_N / 4)) * 4;
            float4 v;
            if (c < QN_)
                v = *(const float4*)(Wq + (size_t)row * QN_ + c);
            else if (c < QN_ + KN_)
                v = *(const float4*)(Wk + (size_t)row * KN_ + (c - QN_));
            else
                v = *(const float4*)(Wv + (size_t)row * KN_ + (c - QN_ - KN_));
            st_half4(Wqkvh + (size_t)row * QKV_N + c, v);
        } else if (u < SEG0 + SEG1 + SEG2) {
            const int j = u - SEG0 - SEG1;
            st_half4(Woh + (size_t)j * 4, *(const float4*)(Wo + (size_t)j * 4));
        } else {
            const int j = u - SEG0 - SEG1 - SEG2;
            const int c = j * 4;
            float4 v;
            if (c < QN_)            v = *(const float4*)(bq + c);
            else if (c < QN_ + KN_) v = *(const float4*)(bk + c - QN_);
            else                    v = *(const float4*)(bv + c - QN_ - KN_);
            *(float4*)(bqkv + c) = v;
        }
    }
}

// ---------------------------------------------------------------------------
// Shared MMA / ldmatrix helpers
// ---------------------------------------------------------------------------
__device__ __forceinline__ void cp_async16(void* smem_dst, const void* gsrc) {
    unsigned dst = (unsigned)__cvta_generic_to_shared(smem_dst);
    asm volatile("cp.async.cg.shared.global [%0], [%1], 16;" :: "r"(dst), "l"(gsrc));
}

__device__ __forceinline__ void ldsm4(unsigned r[4], const void* p)
{
    unsigned a = (unsigned)__cvta_generic_to_shared(p);
    asm volatile(
        "ldmatrix.sync.aligned.m8n8.x4.shared.b16 {%0,%1,%2,%3}, [%4];"
        : "=r"(r[0]), "=r"(r[1]), "=r"(r[2]), "=r"(r[3]) : "r"(a));
}

__device__ __forceinline__ void ldsm4t(unsigned r[4], const void* p)
{
    unsigned a = (unsigned)__cvta_generic_to_shared(p);
    asm volatile(
        "ldmatrix.sync.aligned.m8n8.x4.trans.shared.b16 {%0,%1,%2,%3}, [%4];"
        : "=r"(r[0]), "=r"(r[1]), "=r"(r[2]), "=r"(r[3]) : "r"(a));
}

__device__ __forceinline__ void mma_fp16(float c[4], const unsigned a[4],
                                         unsigned b0, unsigned b1)
{
    asm volatile(
        "mma.sync.aligned.m16n8k16.row.col.f32.f16.f16.f32 "
        "{%0,%1,%2,%3}, {%4,%5,%6,%7}, {%8,%9}, {%0,%1,%2,%3};"
        : "+f"(c[0]), "+f"(c[1]), "+f"(c[2]), "+f"(c[3])
        : "r"(a[0]), "r"(a[1]), "r"(a[2]), "r"(a[3]), "r"(b0), "r"(b1));
}

// ---------------------------------------------------------------------------
// GEMM tiling constants: 128x128 tile, BK=64, 3-stage cp.async.
// A stage: 128 rows x 64 halves (stride 72 -> 144B rows, ldsm conflict-free).
// B stage: 64 rows x 128 halves (stride 136 -> 272B rows).
// ---------------------------------------------------------------------------
#define FA_STR 72
#define FB_STR 136
#define FSTG (128 * FA_STR + 64 * FB_STR)      // 9216 + 8704 = 17920 halves
#define G_SMEM (3 * FSTG * 2)                  // 107520 B
#define TSTR 132
#define QKV_SMEM G_SMEM                        // >= 128*132*4 = 67584

// ---------------------------------------------------------------------------
// Plain FP16 GEMM (O projection), BK=64.
// ---------------------------------------------------------------------------
__global__ __launch_bounds__(256)
void gemm_fp16(const __half* __restrict__ A, const __half* __restrict__ B,
               const float* __restrict__ bias, float* __restrict__ C,
               int M, int N, int K)
{
    extern __shared__ __half gsm[];

    const int tid  = threadIdx.x;
    const int wid  = tid >> 5;
    const int lane = tid & 31;
    const int warp_m = (wid & 1) * 64;
    const int warp_n = (wid >> 1) * 32;
    const int brow = blockIdx.y * 128;
    const int bcol = blockIdx.x * 128;
    const int lr = lane >> 2;
    const int lc = lane & 3;
    const int ldr  = (lane & 7) + ((lane >> 3) & 1) * 8;
    const int ldc8 = ((lane >> 4) & 1) * 8;

    float acc[4][4][4];
#pragma unroll
    for (int mt = 0; mt < 4; mt++)
#pragma unroll
        for (int nt = 0; nt < 4; nt++)
#pragma unroll
            for (int i = 0; i < 4; i++) acc[mt][nt][i] = 0.f;

    auto load_stage = [&](int s, int k0) {
        __half* As = gsm + s * FSTG;
        __half* Bs = As + 128 * FA_STR;
#pragma unroll
        for (int it = 0; it < 4; it++) {       // A: 128 x 64 halves = 1024 chunks
            const int idx = tid + 256 * it;
            const int r = idx >> 3, c = (idx & 7) * 8;
            cp_async16(&As[r * FA_STR + c], &A[(size_t)(brow + r) * K + k0 + c]);
        }
#pragma unroll
        for (int it = 0; it < 4; it++) {       // B: 64 x 128 halves = 1024 chunks
            const int idx = tid + 256 * it;
            const int r = idx >> 4, c = (idx & 15) * 8;
            cp_async16(&Bs[r * FB_STR + c], &B[(size_t)(k0 + r) * N + bcol + c]);
        }
        asm volatile("cp.async.commit_group;");
    };

    const int KT = K / 64;
    load_stage(0, 0);
    load_stage(1, 64);

    for (int kt = 0; kt < KT; kt++) {
        const int s = kt % 3;
        if (kt + 1 < KT) asm volatile("cp.async.wait_group 1;");
        else             asm volatile("cp.async.wait_group 0;");
        __syncthreads();

        if (kt + 2 < KT) load_stage((kt + 2) % 3, (kt + 2) * 64);

        const __half* As = gsm + s * FSTG;
        const __half* Bs = As + 128 * FA_STR;

#pragma unroll
        for (int ks = 0; ks < 4; ks++) {
            unsigned af[4][4];
#pragma unroll
            for (int mt = 0; mt < 4; mt++)
                ldsm4(af[mt], As + (warp_m + mt * 16 + ldr) * FA_STR + ks * 16 + ldc8);

            unsigned bf[4][2];
#pragma unroll
            for (int nt2 = 0; nt2 < 2; nt2++) {
                unsigned t4[4];
                ldsm4t(t4, Bs + (ks * 16 + ldr) * FB_STR + warp_n + nt2 * 16 + ldc8);
                bf[2 * nt2][0]     = t4[0];
                bf[2 * nt2][1]     = t4[1];
                bf[2 * nt2 + 1][0] = t4[2];
                bf[2 * nt2 + 1][1] = t4[3];
            }

#pragma unroll
            for (int mt = 0; mt < 4; mt++)
#pragma unroll
                for (int nt = 0; nt < 4; nt++)
                    mma_fp16(acc[mt][nt], af[mt], bf[nt][0], bf[nt][1]);
        }
    }

#pragma unroll
    for (int mt = 0; mt < 4; mt++) {
#pragma unroll
        for (int nt = 0; nt < 4; nt++) {
            const int row0 = brow + warp_m + mt * 16 + lr;
            const int col  = bcol + warp_n + nt * 8 + lc * 2;
            const float b0 = bias ? bias[col]     : 0.f;
            const float b1 = bias ? bias[col + 1] : 0.f;
            float2 v0 = make_float2(acc[mt][nt][0] + b0, acc[mt][nt][1] + b1);
            float2 v1 = make_float2(acc[mt][nt][2] + b0, acc[mt][nt][3] + b1);
            *(float2*)&C[(size_t)row0 * N + col]       = v0;
            *(float2*)&C[(size_t)(row0 + 8) * N + col] = v1;
        }
    }
}

// ---------------------------------------------------------------------------
// QKV GEMM with fused RoPE epilogue, BK=64 mainloop.
// ---------------------------------------------------------------------------
__global__ __launch_bounds__(256)
void gemm_qkv_rope(const __half* __restrict__ A, const __half* __restrict__ B,
                   const float* __restrict__ bias, const int* __restrict__ pos_ids,
                   __half* __restrict__ Qhi, __half* __restrict__ Qlo,
                   __half* __restrict__ Khi, __half* __restrict__ Klo,
                   __half* __restrict__ Vhi)
{
    extern __shared__ __half gsm[];
    const int N = QKV_N, K = H_;

    const int tid  = threadIdx.x;
    const int wid  = tid >> 5;
    const int lane = tid & 31;
    const int warp_m = (wid & 1) * 64;
    const int warp_n = (wid >> 1) * 32;
    const int brow = blockIdx.y * 128;
    const int bcol = blockIdx.x * 128;
    const int lr = lane >> 2;
    const int lc = lane & 3;
    const int ldr  = (lane & 7) + ((lane >> 3) & 1) * 8;
    const int ldc8 = ((lane >> 4) & 1) * 8;

    float acc[4][4][4];
#pragma unroll
    for (int mt = 0; mt < 4; mt++)
#pragma unroll
        for (int nt = 0; nt < 4; nt++)
#pragma unroll
            for (int i = 0; i < 4; i++) acc[mt][nt][i] = 0.f;

    auto load_stage = [&](int s, int k0) {
        __half* As = gsm + s * FSTG;
        __half* Bs = As + 128 * FA_STR;
#pragma unroll
        for (int it = 0; it < 4; it++) {
            const int idx = tid + 256 * it;
            const int r = idx >> 3, c = (idx & 7) * 8;
            cp_async16(&As[r * FA_STR + c], &A[(size_t)(brow + r) * K + k0 + c]);
        }
#pragma unroll
        for (int it = 0; it < 4; it++) {
            const int idx = tid + 256 * it;
            const int r = idx >> 4, c = (idx & 15) * 8;
            cp_async16(&Bs[r * FB_STR + c], &B[(size_t)(k0 + r) * N + bcol + c]);
        }
        asm volatile("cp.async.commit_group;");
    };

    const int KT = K / 64;
    load_stage(0, 0);
    load_stage(1, 64);

    for (int kt = 0; kt < KT; kt++) {
        const int s = kt % 3;
        if (kt + 1 < KT) asm volatile("cp.async.wait_group 1;");
        else             asm volatile("cp.async.wait_group 0;");
        __syncthreads();

        if (kt + 2 < KT) load_stage((kt + 2) % 3, (kt + 2) * 64);

        const __half* As = gsm + s * FSTG;
        const __half* Bs = As + 128 * FA_STR;

#pragma unroll
        for (int ks = 0; ks < 4; ks++) {
            unsigned af[4][4];
#pragma unroll
            for (int mt = 0; mt < 4; mt++)
                ldsm4(af[mt], As + (warp_m + mt * 16 + ldr) * FA_STR + ks * 16 + ldc8);

            unsigned bf[4][2];
#pragma unroll
            for (int nt2 = 0; nt2 < 2; nt2++) {
                unsigned t4[4];
                ldsm4t(t4, Bs + (ks * 16 + ldr) * FB_STR + warp_n + nt2 * 16 + ldc8);
                bf[2 * nt2][0]     = t4[0];
                bf[2 * nt2][1]     = t4[1];
                bf[2 * nt2 + 1][0] = t4[2];
                bf[2 * nt2 + 1][1] = t4[3];
            }

#pragma unroll
            for (int mt = 0; mt < 4; mt++)
#pragma unroll
                for (int nt = 0; nt < 4; nt++)
                    mma_fp16(acc[mt][nt], af[mt], bf[nt][0], bf[nt][1]);
        }
    }

    // ---- epilogue: stage acc+bias in smem fp32, then rope + fp16 split ----
    __syncthreads();
    float* tile = reinterpret_cast<float*>(gsm);

#pragma unroll
    for (int mt = 0; mt < 4; mt++) {
#pragma unroll
        for (int nt = 0; nt < 4; nt++) {
            const int r0 = warp_m + mt * 16 + lr;
            const int c  = warp_n + nt * 8 + lc * 2;
            const float b0 = bias[bcol + c];
            const float b1 = bias[bcol + c + 1];
            tile[r0 * TSTR + c]           = acc[mt][nt][0] + b0;
            tile[r0 * TSTR + c + 1]       = acc[mt][nt][1] + b1;
            tile[(r0 + 8) * TSTR + c]     = acc[mt][nt][2] + b0;
            tile[(r0 + 8) * TSTR + c + 1] = acc[mt][nt][3] + b1;
        }
    }
    __syncthreads();

    const int head = blockIdx.x;

#pragma unroll
    for (int mt = 0; mt < 4; mt++) {
#pragma unroll
        for (int rr = 0; rr < 2; rr++) {
            const int rl = warp_m + mt * 16 + lr + rr * 8;
            const int grow = brow + rl;
            const int pos = pos_ids[grow];

#pragma unroll
            for (int nt = 0; nt < 4; nt++) {
                const int c = warp_n + nt * 8 + lc * 2;
                float v0 = tile[rl * TSTR + c];
                float v1 = tile[rl * TSTR + c + 1];

                if (head < NH_ + NKV_) {
                    const int poff = (c < 64) ? 64 : -64;
                    const float sgn = (c < 64) ? -1.f : 1.f;
                    const float o0 = sgn * tile[rl * TSTR + c + poff];
                    const float o1 = sgn * tile[rl * TSTR + c + 1 + poff];

                    const int i0 = c & 63, i1 = (c + 1) & 63;
                    float c0, s0, c1, s1;
                    {
                        const float f0 = exp2f(-(float)(2 * i0) * (1.0f / 128.0f) * 13.28771238f);
                        sincosf((float)pos * f0, &s0, &c0);
                        const float f1 = exp2f(-(float)(2 * i1) * (1.0f / 128.0f) * 13.28771238f);
                        sincosf((float)pos * f1, &s1, &c1);
                    }
                    v0 = v0 * c0 + o0 * s0;
                    v1 = v1 * c1 + o1 * s1;

                    if (head < NH_) {
                        v0 *= 0.08838834764831845f;
                        v1 *= 0.08838834764831845f;
                        const size_t off = (size_t)grow * QN_ + head * HD_ + c;
                        __half2 h = __floats2half2_rn(v0, v1);
                        float hx = __low2float(h), hy = __high2float(h);
                        *(__half2*)(Qhi + off) = h;
                        *(__half2*)(Qlo + off) = __floats2half2_rn(v0 - hx, v1 - hy);
                    } else {
                        const size_t off = (size_t)grow * KN_ + (head - NH_) * HD_ + c;
                        __half2 h = __floats2half2_rn(v0, v1);
                        float hx = __low2float(h), hy = __high2float(h);
                        *(__half2*)(Khi + off) = h;
                        *(__half2*)(Klo + off) = __floats2half2_rn(v0 - hx, v1 - hy);
                    }
                } else {
                    const size_t off = (size_t)grow * KN_ + (head - NH_ - NKV_) * HD_ + c;
                    *(__half2*)(Vhi + off) = __floats2half2_rn(v0, v1);
                }
            }
        }
    }
}

// ---------------------------------------------------------------------------
// Tensor-core flash attention (R15, unchanged): BQ=64, double-buffered K+V.
// ---------------------------------------------------------------------------
#define BQ 64
#define BK 64
#define KSTR 136
#define ABUF (BK * KSTR * 2)
#define ASTG (3 * ABUF)
#define ATT_SMEM (2 * ASTG)          // 104448 B

__global__ __launch_bounds__(128)
void attn_mma(const __half* __restrict__ Qhi, const __half* __restrict__ Qlo,
              const __half* __restrict__ Khi, const __half* __restrict__ Klo,
              const __half* __restrict__ Vhi,
              __half* __restrict__ AOh)
{
    extern __shared__ char smraw[];

    const int qt = blockIdx.x, h = blockIdx.y, b = blockIdx.z;
    const int q0 = qt * BQ;
    const int kvh = h >> 2;
    const int tid = threadIdx.x;
    const int w = tid >> 5, lane = tid & 31;
    const int lr = lane >> 2, lc = lane & 3;

    const int qrow0 = q0 + w * 16 + lr;
    const int qrow1 = qrow0 + 8;

    unsigned qa_hi[8][4], qa_lo[8][4];
    {
        const size_t o0 = ((size_t)(b * S_) + qrow0) * QN_ + h * HD_;
        const size_t o1 = ((size_t)(b * S_) + qrow1) * QN_ + h * HD_;
#pragma unroll
        for (int kt = 0; kt < 8; kt++) {
            const int c0 = kt * 16 + 2 * lc;
            qa_hi[kt][0] = *(const unsigned*)(Qhi + o0 + c0);
            qa_hi[kt][1] = *(const unsigned*)(Qhi + o1 + c0);
            qa_hi[kt][2] = *(const unsigned*)(Qhi + o0 + c0 + 8);
            qa_hi[kt][3] = *(const unsigned*)(Qhi + o1 + c0 + 8);
            qa_lo[kt][0] = *(const unsigned*)(Qlo + o0 + c0);
            qa_lo[kt][1] = *(const unsigned*)(Qlo + o1 + c0);
            qa_lo[kt][2] = *(const unsigned*)(Qlo + o0 + c0 + 8);
            qa_lo[kt][3] = *(const unsigned*)(Qlo + o1 + c0 + 8);
        }
    }

    float m0 = -1e30f, m1 = -1e30f, l0 = 0.f, l1 = 0.f;
    float o[16][4];
#pragma unroll
    for (int i = 0; i < 16; i++)
#pragma unroll
        for (int j = 0; j < 4; j++) o[i][j] = 0.f;

    const int nTiles = qt + 1;
    const int wEnd = q0 + w * 16 + 16;
    const int ldr = (lane & 7) + ((lane >> 3) & 1) * 8;
    const int ldc = ((lane >> 4) & 1) * 8;
    const int klr = lane & 7;
    const int kmg = lane >> 3;

    const size_t kv_base = (size_t)(b * S_) * KN_ + kvh * HD_;

    auto load_kv = [&](int s, int kbase) {
        __half* dK  = (__half*)(smraw + s * ASTG);
        __half* dKl = (__half*)(smraw + s * ASTG + ABUF);
        __half* dV  = (__half*)(smraw + s * ASTG + 2 * ABUF);
        const size_t off = kv_base + (size_t)kbase * KN_;
#pragma unroll
        for (int j = 0; j < 8; j++) {
            const int idx = tid + 128 * j;
            const int row = idx >> 4, c16 = idx & 15;
            const size_t g = off + (size_t)row * KN_ + c16 * 8;
            cp_async16(dK  + row * KSTR + c16 * 8, Khi + g);
            cp_async16(dKl + row * KSTR + c16 * 8, Klo + g);
            cp_async16(dV  + row * KSTR + c16 * 8, Vhi + g);
        }
        asm volatile("cp.async.commit_group;");
    };

    load_kv(0, 0);

    for (int kt = 0; kt < nTiles; kt++) {
        const int s = kt & 1;
        const int kbase = kt * BK;
        const bool active = kbase < wEnd;

        asm volatile("cp.async.wait_group 0;");
        __syncthreads();

        if (kt + 1 < nTiles) load_kv(s ^ 1, kbase + BK);

        const __half* sKhi = (const __half*)(smraw + s * ASTG);
        const __half* sKlo = (const __half*)(smraw + s * ASTG + ABUF);
        const __half* sVhi = (const __half*)(smraw + s * ASTG + 2 * ABUF);

        if (active) {
            float sA[8][4];
            unsigned pa[4][4];

#pragma unroll
            for (int nt = 0; nt < 8; nt++)
#pragma unroll
                for (int j = 0; j < 4; j++) sA[nt][j] = 0.f;

#pragma unroll
            for (int dkt2 = 0; dkt2 < 4; dkt2++) {
                const int col = dkt2 * 32 + kmg * 8;
#pragma unroll
                for (int nt = 0; nt < 8; nt++) {
                    unsigned bh[4], bl[4];
                    ldsm4(bh, sKhi + (nt * 8 + klr) * KSTR + col);
                    ldsm4(bl, sKlo + (nt * 8 + klr) * KSTR + col);
                    mma_fp16(sA[nt], qa_hi[2 * dkt2],     bh[0], bh[1]);
                    mma_fp16(sA[nt], qa_hi[2 * dkt2],     bl[0], bl[1]);
                    mma_fp16(sA[nt], qa_lo[2 * dkt2],     bh[0], bh[1]);
                    mma_fp16(sA[nt], qa_hi[2 * dkt2 + 1], bh[2], bh[3]);
                    mma_fp16(sA[nt], qa_hi[2 * dkt2 + 1], bl[2], bl[3]);
                    mma_fp16(sA[nt], qa_lo[2 * dkt2 + 1], bh[2], bh[3]);
                }
            }

            if (kbase + BK > qrow0) {
#pragma unroll
                for (int nt = 0; nt < 8; nt++) {
                    const int j0 = kbase + nt * 8 + 2 * lc;
                    if (j0 > qrow0)     sA[nt][0] = -1e30f;
                    if (j0 + 1 > qrow0) sA[nt][1] = -1e30f;
                    if (j0 > qrow1)     sA[nt][2] = -1e30f;
                    if (j0 + 1 > qrow1) sA[nt][3] = -1e30f;
                }
            }

            float mt0 = -1e30f, mt1 = -1e30f;
#pragma unroll
            for (int nt = 0; nt < 8; nt++) {
                mt0 = fmaxf(mt0, fmaxf(sA[nt][0], sA[nt][1]));
                mt1 = fmaxf(mt1, fmaxf(sA[nt][2], sA[nt][3]));
            }
            mt0 = fmaxf(mt0, __shfl_xor_sync(0xffffffffu, mt0, 1));
            mt0 = fmaxf(mt0, __shfl_xor_sync(0xffffffffu, mt0, 2));
            mt1 = fmaxf(mt1, __shfl_xor_sync(0xffffffffu, mt1, 1));
            mt1 = fmaxf(mt1, __shfl_xor_sync(0xffffffffu, mt1, 2));

            const float nm0 = fmaxf(m0, mt0);
            const float nm1 = fmaxf(m1, mt1);
            const float al0 = __expf(m0 - nm0);
            const float al1 = __expf(m1 - nm1);

            float rs0 = 0.f, rs1 = 0.f;
#pragma unroll
            for (int nt = 0; nt < 8; nt++) {
                sA[nt][0] = __expf(sA[nt][0] - nm0);
                sA[nt][1] = __expf(sA[nt][1] - nm0);
                sA[nt][2] = __expf(sA[nt][2] - nm1);
                sA[nt][3] = __expf(sA[nt][3] - nm1);
                rs0 += sA[nt][0] + sA[nt][1];
                rs1 += sA[nt][2] + sA[nt][3];
            }
            rs0 += __shfl_xor_sync(0xffffffffu, rs0, 1);
            rs0 += __shfl_xor_sync(0xffffffffu, rs0, 2);
            rs1 += __shfl_xor_sync(0xffffffffu, rs1, 1);
            rs1 += __shfl_xor_sync(0xffffffffu, rs1, 2);

            l0 = l0 * al0 + rs0;
            l1 = l1 * al1 + rs1;
            m0 = nm0; m1 = nm1;

#pragma unroll
            for (int i = 0; i < 16; i++) {
                o[i][0] *= al0; o[i][1] *= al0;
                o[i][2] *= al1; o[i][3] *= al1;
            }

#pragma unroll
            for (int t = 0; t < 4; t++) {
                __half2 p0 = __floats2half2_rn(sA[2 * t][0],     sA[2 * t][1]);
                __half2 p1 = __floats2half2_rn(sA[2 * t][2],     sA[2 * t][3]);
                __half2 p2 = __floats2half2_rn(sA[2 * t + 1][0], sA[2 * t + 1][1]);
                __half2 p3 = __floats2half2_rn(sA[2 * t + 1][2], sA[2 * t + 1][3]);
                pa[t][0] = *(unsigned*)&p0;
                pa[t][1] = *(unsigned*)&p1;
                pa[t][2] = *(unsigned*)&p2;
                pa[t][3] = *(unsigned*)&p3;
            }

#pragma unroll
            for (int t = 0; t < 4; t++) {
#pragma unroll
                for (int np = 0; np < 8; np++) {
                    unsigned vh[4];
                    ldsm4t(vh, sVhi + (t * 16 + ldr) * KSTR + np * 16 + ldc);
                    mma_fp16(o[2 * np],     pa[t], vh[0], vh[1]);
                    mma_fp16(o[2 * np + 1], pa[t], vh[2], vh[3]);
                }
            }
        }
    }

    const float il0 = 1.f / l0;
    const float il1 = 1.f / l1;
    __half* O0 = AOh + ((size_t)(b * S_) + qrow0) * QN_ + h * HD_;
    __half* O1 = AOh + ((size_t)(b * S_) + qrow1) * QN_ + h * HD_;
#pragma unroll
    for (int nt = 0; nt < 16; nt++) {
        *(__half2*)(O0 + nt * 8 + 2 * lc) =
            __floats2half2_rn(o[nt][0] * il0, o[nt][1] * il0);
        *(__half2*)(O1 + nt * 8 + 2 * lc) =
            __floats2half2_rn(o[nt][2] * il1, o[nt][3] * il1);
    }
}

// ---------------------------------------------------------------------------
// Launcher
// ---------------------------------------------------------------------------
extern "C" void kernel_launch(void* const* d_in, const int* in_sizes, int n_in,
                              void* d_out, int out_size)
{
    const float* X   = (const float*)d_in[0];
    const int*   pos = (const int*)  d_in[1];
    const float* Wq  = (const float*)d_in[2];
    const float* bq  = (const float*)d_in[3];
    const float* Wk  = (const float*)d_in[4];
    const float* bk  = (const float*)d_in[5];
    const float* Wv  = (const float*)d_in[6];
    const float* bv  = (const float*)d_in[7];
    const float* Wo  = (const float*)d_in[8];
    float* out = (float*)d_out;

    __half *Xh, *Wqkvh, *Woh, *AOh, *Qhi, *Qlo, *Khi, *Klo, *Vhi;
    float *bqkv;
    cudaGetSymbolAddress((void**)&Xh,    g_Xh);
    cudaGetSymbolAddress((void**)&Wqkvh, g_Wqkvh);
    cudaGetSymbolAddress((void**)&bqkv,  g_bqkv);
    cudaGetSymbolAddress((void**)&Woh,   g_Woh);
    cudaGetSymbolAddress((void**)&AOh,   g_AOh);
    cudaGetSymbolAddress((void**)&Qhi,   g_Qhi);
    cudaGetSymbolAddress((void**)&Qlo,   g_Qlo);
    cudaGetSymbolAddress((void**)&Khi,   g_Khi);
    cudaGetSymbolAddress((void**)&Klo,   g_Klo);
    cudaGetSymbolAddress((void**)&Vhi,   g_Vhi);

    cudaFuncSetAttribute(attn_mma,      cudaFuncAttributeMaxDynamicSharedMemorySize, ATT_SMEM);
    cudaFuncSetAttribute(gemm_fp16,     cudaFuncAttributeMaxDynamicSharedMemorySize, G_SMEM);
    cudaFuncSetAttribute(gemm_qkv_rope, cudaFuncAttributeMaxDynamicSharedMemorySize, QKV_SMEM);

    // Fused prep (fp16 rounding + concat + bias)
    prep_all<<<1184, 256>>>(X, Wq, Wk, Wv, Wo, bq, bk, bv, Xh, Wqkvh, Woh, bqkv);

    // Fused QKV projection + RoPE + fp16 splits (BK=64)
    gemm_qkv_rope<<<dim3(QKV_N / 128, M_ / 128), 256, QKV_SMEM>>>(
        Xh, Wqkvh, bqkv, pos, Qhi, Qlo, Khi, Klo, Vhi);

    // Attention (QK 3-MMA, PV 1-MMA), double-buffered K+V
    attn_mma<<<dim3(S_ / BQ, NH_, B_), 128, ATT_SMEM>>>(
        Qhi, Qlo, Khi, Klo, Vhi, AOh);

    // Output projection (fp16 tensor cores, BK=64)
    gemm_fp16<<<dim3(QN_ / 128, M_ / 128), 256, G_SMEM>>>(
        AOh, Woh, nullptr, out, M_, QN_, H_);
}

// round 17
// speedup vs baseline: 1.1290x; 1.0045x over previous
#include <cuda_runtime.h>
#include <cuda_bf16.h>
#include <cuda_fp16.h>
#include <math.h>
#include <stdint.h>

// Problem constants
#define B_  2
#define S_  2048
#define H_  4096
#define NH_ 32
#define NKV_ 8
#define HD_ 128
#define M_  (B_ * S_)          // 4096 rows
#define QN_ (NH_ * HD_)        // 4096
#define KN_ (NKV_ * HD_)       // 1024
#define QKV_N (QN_ + 2 * KN_)  // 6144

// Scratch (device globals; no allocations allowed)
__device__ __half g_Xh[M_ * H_];
__device__ __half g_Wqkvh[H_ * QKV_N];
__device__ float  g_bqkv[QKV_N];
__device__ __half g_Woh[QN_ * H_];
__device__ __half g_AOh[M_ * QN_];
__device__ __half g_Qhi[M_ * QN_], g_Qlo[M_ * QN_];
__device__ __half g_Khi[M_ * KN_], g_Klo[M_ * KN_];
__device__ __half g_Vhi[M_ * KN_];

__device__ __forceinline__ void st_half4(__half* p, float4 v)
{
    *(__half2*)(p)     = __floats2half2_rn(v.x, v.y);
    *(__half2*)(p + 2) = __floats2half2_rn(v.z, v.w);
}

// ---------------------------------------------------------------------------
// Fused prep (unchanged)
// ---------------------------------------------------------------------------
#define SEG0 (M_ * H_ / 4)
#define SEG1 (H_ * QKV_N / 4)
#define SEG2 (QN_ * H_ / 4)
#define SEG3 (QKV_N / 4)
#define SEG_TOTAL (SEG0 + SEG1 + SEG2 + SEG3)

__global__ __launch_bounds__(256)
void prep_all(const float* __restrict__ X,
              const float* __restrict__ Wq, const float* __restrict__ Wk,
              const float* __restrict__ Wv, const float* __restrict__ Wo,
              const float* __restrict__ bq, const float* __restrict__ bk,
              const float* __restrict__ bv,
              __half* __restrict__ Xh, __half* __restrict__ Wqkvh,
              __half* __restrict__ Woh, float* __restrict__ bqkv)
{
    const int stride = gridDim.x * 256;
    for (int u = blockIdx.x * 256 + threadIdx.x; u < SEG_TOTAL; u += stride) {
        if (u < SEG0) {
            st_half4(Xh + (size_t)u * 4, *(const float4*)(X + (size_t)u * 4));
        } else if (u < SEG0 + SEG1) {
            const int j = u - SEG0;
            const int row = j / (QKV_N / 4);
            const int c = (j - row * (QKV_N / 4)) * 4;
            float4 v;
            if (c < QN_)
                v = *(const float4*)(Wq + (size_t)row * QN_ + c);
            else if (c < QN_ + KN_)
                v = *(const float4*)(Wk + (size_t)row * KN_ + (c - QN_));
            else
                v = *(const float4*)(Wv + (size_t)row * KN_ + (c - QN_ - KN_));
            st_half4(Wqkvh + (size_t)row * QKV_N + c, v);
        } else if (u < SEG0 + SEG1 + SEG2) {
            const int j = u - SEG0 - SEG1;
            st_half4(Woh + (size_t)j * 4, *(const float4*)(Wo + (size_t)j * 4));
        } else {
            const int j = u - SEG0 - SEG1 - SEG2;
            const int c = j * 4;
            float4 v;
            if (c < QN_)            v = *(const float4*)(bq + c);
            else if (c < QN_ + KN_) v = *(const float4*)(bk + c - QN_);
            else                    v = *(const float4*)(bv + c - QN_ - KN_);
            *(float4*)(bqkv + c) = v;
        }
    }
}

// ---------------------------------------------------------------------------
// Shared MMA / ldmatrix helpers
// ---------------------------------------------------------------------------
__device__ __forceinline__ void cp_async16(void* smem_dst, const void* gsrc) {
    unsigned dst = (unsigned)__cvta_generic_to_shared(smem_dst);
    asm volatile("cp.async.cg.shared.global [%0], [%1], 16;" :: "r"(dst), "l"(gsrc));
}

__device__ __forceinline__ void ldsm4(unsigned r[4], const void* p)
{
    unsigned a = (unsigned)__cvta_generic_to_shared(p);
    asm volatile(
        "ldmatrix.sync.aligned.m8n8.x4.shared.b16 {%0,%1,%2,%3}, [%4];"
        : "=r"(r[0]), "=r"(r[1]), "=r"(r[2]), "=r"(r[3]) : "r"(a));
}

__device__ __forceinline__ void ldsm4t(unsigned r[4], const void* p)
{
    unsigned a = (unsigned)__cvta_generic_to_shared(p);
    asm volatile(
        "ldmatrix.sync.aligned.m8n8.x4.trans.shared.b16 {%0,%1,%2,%3}, [%4];"
        : "=r"(r[0]), "=r"(r[1]), "=r"(r[2]), "=r"(r[3]) : "r"(a));
}

__device__ __forceinline__ void mma_fp16(float c[4], const unsigned a[4],
                                         unsigned b0, unsigned b1)
{
    asm volatile(
        "mma.sync.aligned.m16n8k16.row.col.f32.f16.f16.f32 "
        "{%0,%1,%2,%3}, {%4,%5,%6,%7}, {%8,%9}, {%0,%1,%2,%3};"
        : "+f"(c[0]), "+f"(c[1]), "+f"(c[2]), "+f"(c[3])
        : "r"(a[0]), "r"(a[1]), "r"(a[2]), "r"(a[3]), "r"(b0), "r"(b1));
}

// ---------------------------------------------------------------------------
// GEMM tiling constants: 128x128 tile, BK=64, 3-stage cp.async (R16).
// ---------------------------------------------------------------------------
#define FA_STR 72
#define FB_STR 136
#define FSTG (128 * FA_STR + 64 * FB_STR)      // 17920 halves
#define G_SMEM (3 * FSTG * 2)                  // 107520 B
#define TSTR 132
#define QKV_SMEM G_SMEM

// ---------------------------------------------------------------------------
// Plain FP16 GEMM (O projection), BK=64 (R16, unchanged).
// ---------------------------------------------------------------------------
__global__ __launch_bounds__(256)
void gemm_fp16(const __half* __restrict__ A, const __half* __restrict__ B,
               const float* __restrict__ bias, float* __restrict__ C,
               int M, int N, int K)
{
    extern __shared__ __half gsm[];

    const int tid  = threadIdx.x;
    const int wid  = tid >> 5;
    const int lane = tid & 31;
    const int warp_m = (wid & 1) * 64;
    const int warp_n = (wid >> 1) * 32;
    const int brow = blockIdx.y * 128;
    const int bcol = blockIdx.x * 128;
    const int lr = lane >> 2;
    const int lc = lane & 3;
    const int ldr  = (lane & 7) + ((lane >> 3) & 1) * 8;
    const int ldc8 = ((lane >> 4) & 1) * 8;

    float acc[4][4][4];
#pragma unroll
    for (int mt = 0; mt < 4; mt++)
#pragma unroll
        for (int nt = 0; nt < 4; nt++)
#pragma unroll
            for (int i = 0; i < 4; i++) acc[mt][nt][i] = 0.f;

    auto load_stage = [&](int s, int k0) {
        __half* As = gsm + s * FSTG;
        __half* Bs = As + 128 * FA_STR;
#pragma unroll
        for (int it = 0; it < 4; it++) {
            const int idx = tid + 256 * it;
            const int r = idx >> 3, c = (idx & 7) * 8;
            cp_async16(&As[r * FA_STR + c], &A[(size_t)(brow + r) * K + k0 + c]);
        }
#pragma unroll
        for (int it = 0; it < 4; it++) {
            const int idx = tid + 256 * it;
            const int r = idx >> 4, c = (idx & 15) * 8;
            cp_async16(&Bs[r * FB_STR + c], &B[(size_t)(k0 + r) * N + bcol + c]);
        }
        asm volatile("cp.async.commit_group;");
    };

    const int KT = K / 64;
    load_stage(0, 0);
    load_stage(1, 64);

    for (int kt = 0; kt < KT; kt++) {
        const int s = kt % 3;
        if (kt + 1 < KT) asm volatile("cp.async.wait_group 1;");
        else             asm volatile("cp.async.wait_group 0;");
        __syncthreads();

        if (kt + 2 < KT) load_stage((kt + 2) % 3, (kt + 2) * 64);

        const __half* As = gsm + s * FSTG;
        const __half* Bs = As + 128 * FA_STR;

#pragma unroll
        for (int ks = 0; ks < 4; ks++) {
            unsigned af[4][4];
#pragma unroll
            for (int mt = 0; mt < 4; mt++)
                ldsm4(af[mt], As + (warp_m + mt * 16 + ldr) * FA_STR + ks * 16 + ldc8);

            unsigned bf[4][2];
#pragma unroll
            for (int nt2 = 0; nt2 < 2; nt2++) {
                unsigned t4[4];
                ldsm4t(t4, Bs + (ks * 16 + ldr) * FB_STR + warp_n + nt2 * 16 + ldc8);
                bf[2 * nt2][0]     = t4[0];
                bf[2 * nt2][1]     = t4[1];
                bf[2 * nt2 + 1][0] = t4[2];
                bf[2 * nt2 + 1][1] = t4[3];
            }

#pragma unroll
            for (int mt = 0; mt < 4; mt++)
#pragma unroll
                for (int nt = 0; nt < 4; nt++)
                    mma_fp16(acc[mt][nt], af[mt], bf[nt][0], bf[nt][1]);
        }
    }

#pragma unroll
    for (int mt = 0; mt < 4; mt++) {
#pragma unroll
        for (int nt = 0; nt < 4; nt++) {
            const int row0 = brow + warp_m + mt * 16 + lr;
            const int col  = bcol + warp_n + nt * 8 + lc * 2;
            const float b0 = bias ? bias[col]     : 0.f;
            const float b1 = bias ? bias[col + 1] : 0.f;
            float2 v0 = make_float2(acc[mt][nt][0] + b0, acc[mt][nt][1] + b1);
            float2 v1 = make_float2(acc[mt][nt][2] + b0, acc[mt][nt][3] + b1);
            *(float2*)&C[(size_t)row0 * N + col]       = v0;
            *(float2*)&C[(size_t)(row0 + 8) * N + col] = v1;
        }
    }
}

// ---------------------------------------------------------------------------
// QKV GEMM with fused RoPE epilogue, BK=64; inv_freq hoisted per nt.
// ---------------------------------------------------------------------------
__global__ __launch_bounds__(256)
void gemm_qkv_rope(const __half* __restrict__ A, const __half* __restrict__ B,
                   const float* __restrict__ bias, const int* __restrict__ pos_ids,
                   __half* __restrict__ Qhi, __half* __restrict__ Qlo,
                   __half* __restrict__ Khi, __half* __restrict__ Klo,
                   __half* __restrict__ Vhi)
{
    extern __shared__ __half gsm[];
    const int N = QKV_N, K = H_;

    const int tid  = threadIdx.x;
    const int wid  = tid >> 5;
    const int lane = tid & 31;
    const int warp_m = (wid & 1) * 64;
    const int warp_n = (wid >> 1) * 32;
    const int brow = blockIdx.y * 128;
    const int bcol = blockIdx.x * 128;
    const int lr = lane >> 2;
    const int lc = lane & 3;
    const int ldr  = (lane & 7) + ((lane >> 3) & 1) * 8;
    const int ldc8 = ((lane >> 4) & 1) * 8;

    float acc[4][4][4];
#pragma unroll
    for (int mt = 0; mt < 4; mt++)
#pragma unroll
        for (int nt = 0; nt < 4; nt++)
#pragma unroll
            for (int i = 0; i < 4; i++) acc[mt][nt][i] = 0.f;

    auto load_stage = [&](int s, int k0) {
        __half* As = gsm + s * FSTG;
        __half* Bs = As + 128 * FA_STR;
#pragma unroll
        for (int it = 0; it < 4; it++) {
            const int idx = tid + 256 * it;
            const int r = idx >> 3, c = (idx & 7) * 8;
            cp_async16(&As[r * FA_STR + c], &A[(size_t)(brow + r) * K + k0 + c]);
        }
#pragma unroll
        for (int it = 0; it < 4; it++) {
            const int idx = tid + 256 * it;
            const int r = idx >> 4, c = (idx & 15) * 8;
            cp_async16(&Bs[r * FB_STR + c], &B[(size_t)(k0 + r) * N + bcol + c]);
        }
        asm volatile("cp.async.commit_group;");
    };

    const int KT = K / 64;
    load_stage(0, 0);
    load_stage(1, 64);

    for (int kt = 0; kt < KT; kt++) {
        const int s = kt % 3;
        if (kt + 1 < KT) asm volatile("cp.async.wait_group 1;");
        else             asm volatile("cp.async.wait_group 0;");
        __syncthreads();

        if (kt + 2 < KT) load_stage((kt + 2) % 3, (kt + 2) * 64);

        const __half* As = gsm + s * FSTG;
        const __half* Bs = As + 128 * FA_STR;

#pragma unroll
        for (int ks = 0; ks < 4; ks++) {
            unsigned af[4][4];
#pragma unroll
            for (int mt = 0; mt < 4; mt++)
                ldsm4(af[mt], As + (warp_m + mt * 16 + ldr) * FA_STR + ks * 16 + ldc8);

            unsigned bf[4][2];
#pragma unroll
            for (int nt2 = 0; nt2 < 2; nt2++) {
                unsigned t4[4];
                ldsm4t(t4, Bs + (ks * 16 + ldr) * FB_STR + warp_n + nt2 * 16 + ldc8);
                bf[2 * nt2][0]     = t4[0];
                bf[2 * nt2][1]     = t4[1];
                bf[2 * nt2 + 1][0] = t4[2];
                bf[2 * nt2 + 1][1] = t4[3];
            }

#pragma unroll
            for (int mt = 0; mt < 4; mt++)
#pragma unroll
                for (int nt = 0; nt < 4; nt++)
                    mma_fp16(acc[mt][nt], af[mt], bf[nt][0], bf[nt][1]);
        }
    }

    // ---- epilogue: stage acc+bias in smem fp32, then rope + fp16 split ----
    __syncthreads();
    float* tile = reinterpret_cast<float*>(gsm);

#pragma unroll
    for (int mt = 0; mt < 4; mt++) {
#pragma unroll
        for (int nt = 0; nt < 4; nt++) {
            const int r0 = warp_m + mt * 16 + lr;
            const int c  = warp_n + nt * 8 + lc * 2;
            const float b0 = bias[bcol + c];
            const float b1 = bias[bcol + c + 1];
            tile[r0 * TSTR + c]           = acc[mt][nt][0] + b0;
            tile[r0 * TSTR + c + 1]       = acc[mt][nt][1] + b1;
            tile[(r0 + 8) * TSTR + c]     = acc[mt][nt][2] + b0;
            tile[(r0 + 8) * TSTR + c + 1] = acc[mt][nt][3] + b1;
        }
    }
    __syncthreads();

    const int head = blockIdx.x;

    // hoisted inv_freq per nt (identical expressions -> identical values)
    float invf0[4], invf1[4];
#pragma unroll
    for (int nt = 0; nt < 4; nt++) {
        const int c = warp_n + nt * 8 + lc * 2;
        const int i0 = c & 63, i1 = (c + 1) & 63;
        invf0[nt] = exp2f(-(float)(2 * i0) * (1.0f / 128.0f) * 13.28771238f);
        invf1[nt] = exp2f(-(float)(2 * i1) * (1.0f / 128.0f) * 13.28771238f);
    }

#pragma unroll
    for (int mt = 0; mt < 4; mt++) {
#pragma unroll
        for (int rr = 0; rr < 2; rr++) {
            const int rl = warp_m + mt * 16 + lr + rr * 8;
            const int grow = brow + rl;
            const int pos = pos_ids[grow];

#pragma unroll
            for (int nt = 0; nt < 4; nt++) {
                const int c = warp_n + nt * 8 + lc * 2;
                float v0 = tile[rl * TSTR + c];
                float v1 = tile[rl * TSTR + c + 1];

                if (head < NH_ + NKV_) {
                    const int poff = (c < 64) ? 64 : -64;
                    const float sgn = (c < 64) ? -1.f : 1.f;
                    const float o0 = sgn * tile[rl * TSTR + c + poff];
                    const float o1 = sgn * tile[rl * TSTR + c + 1 + poff];

                    float c0, s0, c1, s1;
                    sincosf((float)pos * invf0[nt], &s0, &c0);
                    sincosf((float)pos * invf1[nt], &s1, &c1);
                    v0 = v0 * c0 + o0 * s0;
                    v1 = v1 * c1 + o1 * s1;

                    if (head < NH_) {
                        v0 *= 0.08838834764831845f;
                        v1 *= 0.08838834764831845f;
                        const size_t off = (size_t)grow * QN_ + head * HD_ + c;
                        __half2 h = __floats2half2_rn(v0, v1);
                        float hx = __low2float(h), hy = __high2float(h);
                        *(__half2*)(Qhi + off) = h;
                        *(__half2*)(Qlo + off) = __floats2half2_rn(v0 - hx, v1 - hy);
                    } else {
                        const size_t off = (size_t)grow * KN_ + (head - NH_) * HD_ + c;
                        __half2 h = __floats2half2_rn(v0, v1);
                        float hx = __low2float(h), hy = __high2float(h);
                        *(__half2*)(Khi + off) = h;
                        *(__half2*)(Klo + off) = __floats2half2_rn(v0 - hx, v1 - hy);
                    }
                } else {
                    const size_t off = (size_t)grow * KN_ + (head - NH_ - NKV_) * HD_ + c;
                    *(__half2*)(Vhi + off) = __floats2half2_rn(v0, v1);
                }
            }
        }
    }
}

// ---------------------------------------------------------------------------
// Tensor-core flash attention (R15 core): BQ=64, double-buffered K+V.
// Heavy-first scheduling: qt reversed so heaviest causal blocks launch first.
// ---------------------------------------------------------------------------
#define BQ 64
#define BK 64
#define KSTR 136
#define ABUF (BK * KSTR * 2)
#define ASTG (3 * ABUF)
#define ATT_SMEM (2 * ASTG)          // 104448 B

__global__ __launch_bounds__(128)
void attn_mma(const __half* __restrict__ Qhi, const __half* __restrict__ Qlo,
              const __half* __restrict__ Khi, const __half* __restrict__ Klo,
              const __half* __restrict__ Vhi,
              __half* __restrict__ AOh)
{
    extern __shared__ char smraw[];

    const int qt = gridDim.x - 1 - blockIdx.x;   // heavy blocks first
    const int h = blockIdx.y, b = blockIdx.z;
    const int q0 = qt * BQ;
    const int kvh = h >> 2;
    const int tid = threadIdx.x;
    const int w = tid >> 5, lane = tid & 31;
    const int lr = lane >> 2, lc = lane & 3;

    const int qrow0 = q0 + w * 16 + lr;
    const int qrow1 = qrow0 + 8;

    unsigned qa_hi[8][4], qa_lo[8][4];
    {
        const size_t o0 = ((size_t)(b * S_) + qrow0) * QN_ + h * HD_;
        const size_t o1 = ((size_t)(b * S_) + qrow1) * QN_ + h * HD_;
#pragma unroll
        for (int kt = 0; kt < 8; kt++) {
            const int c0 = kt * 16 + 2 * lc;
            qa_hi[kt][0] = *(const unsigned*)(Qhi + o0 + c0);
            qa_hi[kt][1] = *(const unsigned*)(Qhi + o1 + c0);
            qa_hi[kt][2] = *(const unsigned*)(Qhi + o0 + c0 + 8);
            qa_hi[kt][3] = *(const unsigned*)(Qhi + o1 + c0 + 8);
            qa_lo[kt][0] = *(const unsigned*)(Qlo + o0 + c0);
            qa_lo[kt][1] = *(const unsigned*)(Qlo + o1 + c0);
            qa_lo[kt][2] = *(const unsigned*)(Qlo + o0 + c0 + 8);
            qa_lo[kt][3] = *(const unsigned*)(Qlo + o1 + c0 + 8);
        }
    }

    float m0 = -1e30f, m1 = -1e30f, l0 = 0.f, l1 = 0.f;
    float o[16][4];
#pragma unroll
    for (int i = 0; i < 16; i++)
#pragma unroll
        for (int j = 0; j < 4; j++) o[i][j] = 0.f;

    const int nTiles = qt + 1;
    const int wEnd = q0 + w * 16 + 16;
    const int ldr = (lane & 7) + ((lane >> 3) & 1) * 8;
    const int ldc = ((lane >> 4) & 1) * 8;
    const int klr = lane & 7;
    const int kmg = lane >> 3;

    const size_t kv_base = (size_t)(b * S_) * KN_ + kvh * HD_;

    auto load_kv = [&](int s, int kbase) {
        __half* dK  = (__half*)(smraw + s * ASTG);
        __half* dKl = (__half*)(smraw + s * ASTG + ABUF);
        __half* dV  = (__half*)(smraw + s * ASTG + 2 * ABUF);
        const size_t off = kv_base + (size_t)kbase * KN_;
#pragma unroll
        for (int j = 0; j < 8; j++) {
            const int idx = tid + 128 * j;
            const int row = idx >> 4, c16 = idx & 15;
            const size_t g = off + (size_t)row * KN_ + c16 * 8;
            cp_async16(dK  + row * KSTR + c16 * 8, Khi + g);
            cp_async16(dKl + row * KSTR + c16 * 8, Klo + g);
            cp_async16(dV  + row * KSTR + c16 * 8, Vhi + g);
        }
        asm volatile("cp.async.commit_group;");
    };

    load_kv(0, 0);

    for (int kt = 0; kt < nTiles; kt++) {
        const int s = kt & 1;
        const int kbase = kt * BK;
        const bool active = kbase < wEnd;

        asm volatile("cp.async.wait_group 0;");
        __syncthreads();

        if (kt + 1 < nTiles) load_kv(s ^ 1, kbase + BK);

        const __half* sKhi = (const __half*)(smraw + s * ASTG);
        const __half* sKlo = (const __half*)(smraw + s * ASTG + ABUF);
        const __half* sVhi = (const __half*)(smraw + s * ASTG + 2 * ABUF);

        if (active) {
            float sA[8][4];
            unsigned pa[4][4];

#pragma unroll
            for (int nt = 0; nt < 8; nt++)
#pragma unroll
                for (int j = 0; j < 4; j++) sA[nt][j] = 0.f;

#pragma unroll
            for (int dkt2 = 0; dkt2 < 4; dkt2++) {
                const int col = dkt2 * 32 + kmg * 8;
#pragma unroll
                for (int nt = 0; nt < 8; nt++) {
                    unsigned bh[4], bl[4];
                    ldsm4(bh, sKhi + (nt * 8 + klr) * KSTR + col);
                    ldsm4(bl, sKlo + (nt * 8 + klr) * KSTR + col);
                    mma_fp16(sA[nt], qa_hi[2 * dkt2],     bh[0], bh[1]);
                    mma_fp16(sA[nt], qa_hi[2 * dkt2],     bl[0], bl[1]);
                    mma_fp16(sA[nt], qa_lo[2 * dkt2],     bh[0], bh[1]);
                    mma_fp16(sA[nt], qa_hi[2 * dkt2 + 1], bh[2], bh[3]);
                    mma_fp16(sA[nt], qa_hi[2 * dkt2 + 1], bl[2], bl[3]);
                    mma_fp16(sA[nt], qa_lo[2 * dkt2 + 1], bh[2], bh[3]);
                }
            }

            if (kbase + BK > qrow0) {
#pragma unroll
                for (int nt = 0; nt < 8; nt++) {
                    const int j0 = kbase + nt * 8 + 2 * lc;
                    if (j0 > qrow0)     sA[nt][0] = -1e30f;
                    if (j0 + 1 > qrow0) sA[nt][1] = -1e30f;
                    if (j0 > qrow1)     sA[nt][2] = -1e30f;
                    if (j0 + 1 > qrow1) sA[nt][3] = -1e30f;
                }
            }

            float mt0 = -1e30f, mt1 = -1e30f;
#pragma unroll
            for (int nt = 0; nt < 8; nt++) {
                mt0 = fmaxf(mt0, fmaxf(sA[nt][0], sA[nt][1]));
                mt1 = fmaxf(mt1, fmaxf(sA[nt][2], sA[nt][3]));
            }
            mt0 = fmaxf(mt0, __shfl_xor_sync(0xffffffffu, mt0, 1));
            mt0 = fmaxf(mt0, __shfl_xor_sync(0xffffffffu, mt0, 2));
            mt1 = fmaxf(mt1, __shfl_xor_sync(0xffffffffu, mt1, 1));
            mt1 = fmaxf(mt1, __shfl_xor_sync(0xffffffffu, mt1, 2));

            const float nm0 = fmaxf(m0, mt0);
            const float nm1 = fmaxf(m1, mt1);
            const float al0 = __expf(m0 - nm0);
            const float al1 = __expf(m1 - nm1);

            float rs0 = 0.f, rs1 = 0.f;
#pragma unroll
            for (int nt = 0; nt < 8; nt++) {
                sA[nt][0] = __expf(sA[nt][0] - nm0);
                sA[nt][1] = __expf(sA[nt][1] - nm0);
                sA[nt][2] = __expf(sA[nt][2] - nm1);
                sA[nt][3] = __expf(sA[nt][3] - nm1);
                rs0 += sA[nt][0] + sA[nt][1];
                rs1 += sA[nt][2] + sA[nt][3];
            }
            rs0 += __shfl_xor_sync(0xffffffffu, rs0, 1);
            rs0 += __shfl_xor_sync(0xffffffffu, rs0, 2);
            rs1 += __shfl_xor_sync(0xffffffffu, rs1, 1);
            rs1 += __shfl_xor_sync(0xffffffffu, rs1, 2);

            l0 = l0 * al0 + rs0;
            l1 = l1 * al1 + rs1;
            m0 = nm0; m1 = nm1;

#pragma unroll
            for (int i = 0; i < 16; i++) {
                o[i][0] *= al0; o[i][1] *= al0;
                o[i][2] *= al1; o[i][3] *= al1;
            }

#pragma unroll
            for (int t = 0; t < 4; t++) {
                __half2 p0 = __floats2half2_rn(sA[2 * t][0],     sA[2 * t][1]);
                __half2 p1 = __floats2half2_rn(sA[2 * t][2],     sA[2 * t][3]);
                __half2 p2 = __floats2half2_rn(sA[2 * t + 1][0], sA[2 * t + 1][1]);
                __half2 p3 = __floats2half2_rn(sA[2 * t + 1][2], sA[2 * t + 1][3]);
                pa[t][0] = *(unsigned*)&p0;
                pa[t][1] = *(unsigned*)&p1;
                pa[t][2] = *(unsigned*)&p2;
                pa[t][3] = *(unsigned*)&p3;
            }

#pragma unroll
            for (int t = 0; t < 4; t++) {
#pragma unroll
                for (int np = 0; np < 8; np++) {
                    unsigned vh[4];
                    ldsm4t(vh, sVhi + (t * 16 + ldr) * KSTR + np * 16 + ldc);
                    mma_fp16(o[2 * np],     pa[t], vh[0], vh[1]);
                    mma_fp16(o[2 * np + 1], pa[t], vh[2], vh[3]);
                }
            }
        }
    }

    const float il0 = 1.f / l0;
    const float il1 = 1.f / l1;
    __half* O0 = AOh + ((size_t)(b * S_) + qrow0) * QN_ + h * HD_;
    __half* O1 = AOh + ((size_t)(b * S_) + qrow1) * QN_ + h * HD_;
#pragma unroll
    for (int nt = 0; nt < 16; nt++) {
        *(__half2*)(O0 + nt * 8 + 2 * lc) =
            __floats2half2_rn(o[nt][0] * il0, o[nt][1] * il0);
        *(__half2*)(O1 + nt * 8 + 2 * lc) =
            __floats2half2_rn(o[nt][2] * il1, o[nt][3] * il1);
    }
}

// ---------------------------------------------------------------------------
// Launcher
// ---------------------------------------------------------------------------
extern "C" void kernel_launch(void* const* d_in, const int* in_sizes, int n_in,
                              void* d_out, int out_size)
{
    const float* X   = (const float*)d_in[0];
    const int*   pos = (const int*)  d_in[1];
    const float* Wq  = (const float*)d_in[2];
    const float* bq  = (const float*)d_in[3];
    const float* Wk  = (const float*)d_in[4];
    const float* bk  = (const float*)d_in[5];
    const float* Wv  = (const float*)d_in[6];
    const float* bv  = (const float*)d_in[7];
    const float* Wo  = (const float*)d_in[8];
    float* out = (float*)d_out;

    __half *Xh, *Wqkvh, *Woh, *AOh, *Qhi, *Qlo, *Khi, *Klo, *Vhi;
    float *bqkv;
    cudaGetSymbolAddress((void**)&Xh,    g_Xh);
    cudaGetSymbolAddress((void**)&Wqkvh, g_Wqkvh);
    cudaGetSymbolAddress((void**)&bqkv,  g_bqkv);
    cudaGetSymbolAddress((void**)&Woh,   g_Woh);
    cudaGetSymbolAddress((void**)&AOh,   g_AOh);
    cudaGetSymbolAddress((void**)&Qhi,   g_Qhi);
    cudaGetSymbolAddress((void**)&Qlo,   g_Qlo);
    cudaGetSymbolAddress((void**)&Khi,   g_Khi);
    cudaGetSymbolAddress((void**)&Klo,   g_Klo);
    cudaGetSymbolAddress((void**)&Vhi,   g_Vhi);

    cudaFuncSetAttribute(attn_mma,      cudaFuncAttributeMaxDynamicSharedMemorySize, ATT_SMEM);
    cudaFuncSetAttribute(gemm_fp16,     cudaFuncAttributeMaxDynamicSharedMemorySize, G_SMEM);
    cudaFuncSetAttribute(gemm_qkv_rope, cudaFuncAttributeMaxDynamicSharedMemorySize, QKV_SMEM);

    // Fused prep (fp16 rounding + concat + bias)
    prep_all<<<1184, 256>>>(X, Wq, Wk, Wv, Wo, bq, bk, bv, Xh, Wqkvh, Woh, bqkv);

    // Fused QKV projection + RoPE + fp16 splits (BK=64)
    gemm_qkv_rope<<<dim3(QKV_N / 128, M_ / 128), 256, QKV_SMEM>>>(
        Xh, Wqkvh, bqkv, pos, Qhi, Qlo, Khi, Klo, Vhi);

    // Attention (QK 3-MMA, PV 1-MMA), double-buffered K+V, heavy-first order
    attn_mma<<<dim3(S_ / BQ, NH_, B_), 128, ATT_SMEM>>>(
        Qhi, Qlo, Khi, Klo, Vhi, AOh);

    // Output projection (fp16 tensor cores, BK=64)
    gemm_fp16<<<dim3(QN_ / 128, M_ / 128), 256, G_SMEM>>>(
        AOh, Woh, nullptr, out, M_, QN_, H_);
}